// round 2
// baseline (speedup 1.0000x reference)
#include <cuda_runtime.h>
#include <cuda_bf16.h>
#include <cstdint>

#define NB 256
#define TT 128
#define DD 1024
#define HH 1024
#define LL 49
#define K3 3072
#define N4 4096

typedef __nv_bfloat16 bf;

// ---------------- scratch (static device globals; no runtime allocation) ----------------
__device__ __align__(256) bf    g_Xhi[TT * NB * DD];   // x split hi, layout [t][n][k]
__device__ __align__(256) bf    g_Xlo[TT * NB * DD];   // x split lo
__device__ __align__(256) bf    g_Whi[N4 * K3];        // W concat transposed [n][k], hi
__device__ __align__(256) bf    g_Wlo[N4 * K3];        // lo
__device__ __align__(256) float g_h[NB * HH];
__device__ __align__(256) float g_c[NB * HH];
__device__ __align__(256) bf    g_hhi[NB * HH];
__device__ __align__(256) bf    g_hlo[NB * HH];
__device__ __align__(256) bf    g_ahi[NB * HH];        // attn split
__device__ __align__(256) bf    g_alo[NB * HH];
__device__ __align__(256) float g_P0[NB * N4];         // split-K partial 0
__device__ __align__(256) float g_P1[NB * N4];         // split-K partial 1

__device__ __forceinline__ void split2(float v, bf& hi, bf& lo) {
    hi = __float2bfloat16(v);
    lo = __float2bfloat16(v - __bfloat162float(hi));
}

__device__ __forceinline__ void cp16(const bf* smem_dst, const bf* gsrc) {
    unsigned s = (unsigned)__cvta_generic_to_shared((void*)smem_dst);
    asm volatile("cp.async.cg.shared.global [%0], [%1], 16;\n" :: "r"(s), "l"(gsrc));
}

__device__ __forceinline__ void mma16816(float* d, const unsigned* a, const unsigned* b) {
    asm volatile(
        "mma.sync.aligned.m16n8k16.row.col.f32.bf16.bf16.f32 "
        "{%0,%1,%2,%3}, {%4,%5,%6,%7}, {%8,%9}, {%0,%1,%2,%3};\n"
        : "+f"(d[0]), "+f"(d[1]), "+f"(d[2]), "+f"(d[3])
        : "r"(a[0]), "r"(a[1]), "r"(a[2]), "r"(a[3]), "r"(b[0]), "r"(b[1]));
}

// ---------------- prep: split x into [t][n][k] bf16 hi/lo ----------------
__global__ void __launch_bounds__(256) k_prepX(const float* __restrict__ x) {
    int idx = blockIdx.x * 256 + threadIdx.x;     // over T*N*D, x is (N,T,D)
    int k = idx & 1023;
    int r = idx >> 10;                            // n*TT + t
    int t = r & 127;
    int n = r >> 7;
    float v = x[idx];
    bf hi, lo; split2(v, hi, lo);
    int o = (t * NB + n) * DD + k;
    g_Xhi[o] = hi;
    g_Xlo[o] = lo;
}

// ---------------- prep: transpose + split weights into [n][k] concat ----------------
__global__ void k_prepW(const float* __restrict__ Wx, const float* __restrict__ Wh,
                        const float* __restrict__ Wattn) {
    __shared__ float tile[32][33];
    int k0 = blockIdx.x * 32, n0 = blockIdx.y * 32;
    int tx = threadIdx.x, ty = threadIdx.y;       // block (32,8)
    const float* src; int kb;
    if (k0 < 1024)      { src = Wx;    kb = 0; }
    else if (k0 < 2048) { src = Wh;    kb = 1024; }
    else                { src = Wattn; kb = 2048; }
    #pragma unroll
    for (int i = 0; i < 4; ++i) {
        int r = ty + i * 8;
        tile[r][tx] = src[(k0 - kb + r) * N4 + n0 + tx];
    }
    __syncthreads();
    #pragma unroll
    for (int i = 0; i < 4; ++i) {
        int r = ty + i * 8;
        int n = n0 + r, k = k0 + tx;
        float v = tile[tx][r];
        bf hi, lo; split2(v, hi, lo);
        g_Whi[n * K3 + k] = hi;
        g_Wlo[n * K3 + k] = lo;
    }
}

// ---------------- prep: h0 = c0 = mean over spatial dims of A ----------------
__global__ void __launch_bounds__(256) k_init(const float* __restrict__ A) {
    int idx = blockIdx.x * 256 + threadIdx.x;     // over NB*HH
    const float* Ap = A + (size_t)idx * LL;
    float s = 0.f;
    #pragma unroll
    for (int l = 0; l < LL; ++l) s += Ap[l];
    s *= (1.f / 49.f);
    g_h[idx] = s;
    g_c[idx] = s;
    bf hi, lo; split2(s, hi, lo);
    g_hhi[idx] = hi;
    g_hlo[idx] = lo;
}

// ---------------- per-step attention: scores -> softmax -> attn (split bf16) ----------------
__global__ void __launch_bounds__(256) k_att(const float* __restrict__ A) {
    int n = blockIdx.x;
    int tid = threadIdx.x;
    int lane = tid & 31, wid = tid >> 5;
    __shared__ float red[8][LL];
    __shared__ float sw[LL];

    float acc[LL];
    #pragma unroll
    for (int l = 0; l < LL; ++l) acc[l] = 0.f;

    const float* Abase = A + (size_t)n * HH * LL;
    for (int hh = tid; hh < HH; hh += 256) {
        float hv = g_h[n * HH + hh];
        const float* Ap = Abase + hh * LL;
        #pragma unroll
        for (int l = 0; l < LL; ++l) acc[l] += hv * Ap[l];
    }
    #pragma unroll
    for (int l = 0; l < LL; ++l) {
        #pragma unroll
        for (int off = 16; off; off >>= 1)
            acc[l] += __shfl_xor_sync(0xffffffffu, acc[l], off);
    }
    if (lane == 0) {
        #pragma unroll
        for (int l = 0; l < LL; ++l) red[wid][l] = acc[l];
    }
    __syncthreads();
    if (tid < LL) {
        float s = 0.f;
        #pragma unroll
        for (int w = 0; w < 8; ++w) s += red[w][tid];
        sw[tid] = s * 0.03125f;     // 1/sqrt(H)
    }
    __syncthreads();
    if (tid == 0) {
        float m = -1e30f;
        for (int l = 0; l < LL; ++l) m = fmaxf(m, sw[l]);
        float s = 0.f;
        for (int l = 0; l < LL; ++l) { float e = expf(sw[l] - m); sw[l] = e; s += e; }
        float inv = 1.f / s;
        for (int l = 0; l < LL; ++l) sw[l] *= inv;
    }
    __syncthreads();
    for (int hh = tid; hh < HH; hh += 256) {
        const float* Ap = Abase + hh * LL;   // hot in L1 from pass 1
        float d = 0.f;
        #pragma unroll
        for (int l = 0; l < LL; ++l) d += sw[l] * Ap[l];
        bf hi, lo; split2(d, hi, lo);
        g_ahi[n * HH + hh] = hi;
        g_alo[n * HH + hh] = lo;
    }
}

// ---------------- per-step GEMM: [x_t | h | attn](256x3072) @ W^T(3072x4096), split-K=2 ----------------
// bf16 2-way split (hi/lo): C = Ah*Bh + Ah*Bl + Al*Bh  (fp32 accumulate)
#define SMS 5120   // 128*40 bf16 per stage per matrix

__device__ __forceinline__ void gemm_load_chunk(int t, int kc, int buf, int bm, int bn, int tid,
                                                bf* sAh, bf* sAl, bf* sBh, bf* sBl) {
    const bf *pAh, *pAl; int kb;
    if (kc < 1024)      { int o = t * (NB * DD); pAh = g_Xhi + o; pAl = g_Xlo + o; kb = 0; }
    else if (kc < 2048) { pAh = g_hhi; pAl = g_hlo; kb = 1024; }
    else                { pAh = g_ahi; pAl = g_alo; kb = 2048; }
    const int kA = kc - kb;
    #pragma unroll
    for (int j = 0; j < 2; ++j) {
        int v = tid + 256 * j;
        int row = v >> 2, cq = v & 3;
        int soff = buf * SMS + row * 40 + cq * 8;
        int gA = (bm * 128 + row) * 1024 + kA + cq * 8;
        int gB = (bn * 128 + row) * K3 + kc + cq * 8;
        cp16(sAh + soff, pAh + gA);
        cp16(sAl + soff, pAl + gA);
        cp16(sBh + soff, g_Whi + gB);
        cp16(sBl + soff, g_Wlo + gB);
    }
    asm volatile("cp.async.commit_group;\n" ::);
}

__global__ void __launch_bounds__(256, 1) k_gemm(int t) {
    const int bm = blockIdx.x;   // 0..1
    const int bn = blockIdx.y;   // 0..31
    const int z  = blockIdx.z;   // 0..1 split-K
    extern __shared__ bf sm[];
    bf* sAh = sm;
    bf* sAl = sm + 2 * SMS;
    bf* sBh = sm + 4 * SMS;
    bf* sBl = sm + 6 * SMS;
    const int tid  = threadIdx.x;
    const int lane = tid & 31, w = tid >> 5;
    const int wm = w & 1, wn = w >> 1;          // 2x4 warp grid, warp tile 64x32
    const int lr = lane >> 2, lc = lane & 3;

    float d[4][4][4];
    #pragma unroll
    for (int a = 0; a < 4; ++a)
        #pragma unroll
        for (int b2 = 0; b2 < 4; ++b2)
            #pragma unroll
            for (int c = 0; c < 4; ++c) d[a][b2][c] = 0.f;

    const int kc0 = z * 1536;
    gemm_load_chunk(t, kc0, 0, bm, bn, tid, sAh, sAl, sBh, sBl);

    for (int it = 0; it < 48; ++it) {
        asm volatile("cp.async.wait_group 0;\n" ::);
        __syncthreads();
        if (it + 1 < 48)
            gemm_load_chunk(t, kc0 + (it + 1) * 32, (it + 1) & 1, bm, bn, tid, sAh, sAl, sBh, sBl);
        const int buf = it & 1;
        const bf* Ah = sAh + buf * SMS;
        const bf* Al = sAl + buf * SMS;
        const bf* Bh = sBh + buf * SMS;
        const bf* Bl = sBl + buf * SMS;
        #pragma unroll
        for (int kt = 0; kt < 32; kt += 16) {
            unsigned ah[4][4], al[4][4], bh[4][2], bl[4][2];
            #pragma unroll
            for (int mt = 0; mt < 4; ++mt) {
                int r0 = wm * 64 + mt * 16 + lr;
                int c0 = kt + lc * 2;
                ah[mt][0] = *(const unsigned*)(Ah + r0 * 40 + c0);
                ah[mt][1] = *(const unsigned*)(Ah + (r0 + 8) * 40 + c0);
                ah[mt][2] = *(const unsigned*)(Ah + r0 * 40 + c0 + 8);
                ah[mt][3] = *(const unsigned*)(Ah + (r0 + 8) * 40 + c0 + 8);
                al[mt][0] = *(const unsigned*)(Al + r0 * 40 + c0);
                al[mt][1] = *(const unsigned*)(Al + (r0 + 8) * 40 + c0);
                al[mt][2] = *(const unsigned*)(Al + r0 * 40 + c0 + 8);
                al[mt][3] = *(const unsigned*)(Al + (r0 + 8) * 40 + c0 + 8);
            }
            #pragma unroll
            for (int nt = 0; nt < 4; ++nt) {
                int rB = wn * 32 + nt * 8 + lr;
                int cB = kt + lc * 2;
                bh[nt][0] = *(const unsigned*)(Bh + rB * 40 + cB);
                bh[nt][1] = *(const unsigned*)(Bh + rB * 40 + cB + 8);
                bl[nt][0] = *(const unsigned*)(Bl + rB * 40 + cB);
                bl[nt][1] = *(const unsigned*)(Bl + rB * 40 + cB + 8);
            }
            #pragma unroll
            for (int mt = 0; mt < 4; ++mt)
                #pragma unroll
                for (int nt = 0; nt < 4; ++nt) {
                    mma16816(d[mt][nt], ah[mt], bh[nt]);
                    mma16816(d[mt][nt], ah[mt], bl[nt]);
                    mma16816(d[mt][nt], al[mt], bh[nt]);
                }
        }
        __syncthreads();
    }

    float* P = z ? g_P1 : g_P0;
    #pragma unroll
    for (int mt = 0; mt < 4; ++mt) {
        int r = bm * 128 + wm * 64 + mt * 16 + lr;
        #pragma unroll
        for (int nt = 0; nt < 4; ++nt) {
            int cN = bn * 128 + wn * 32 + nt * 8 + 2 * lc;
            float2 v0 = make_float2(d[mt][nt][0], d[mt][nt][1]);
            float2 v1 = make_float2(d[mt][nt][2], d[mt][nt][3]);
            *(float2*)&P[r * N4 + cN]       = v0;
            *(float2*)&P[(r + 8) * N4 + cN] = v1;
        }
    }
}

// ---------------- per-step gates + state update + output + h split ----------------
__global__ void __launch_bounds__(256) k_gates(const float* __restrict__ bvec,
                                               float* __restrict__ out, int t) {
    int idx = blockIdx.x * 256 + threadIdx.x;    // over NB*HH
    int n = idx >> 10, j = idx & 1023;
    int base = n * N4 + j;
    float a0 = g_P0[base]          + g_P1[base]          + bvec[j];
    float a1 = g_P0[base + 1024]   + g_P1[base + 1024]   + bvec[j + 1024];
    float a2 = g_P0[base + 2048]   + g_P1[base + 2048]   + bvec[j + 2048];
    float a3 = g_P0[base + 3072]   + g_P1[base + 3072]   + bvec[j + 3072];
    float ig = 1.f / (1.f + expf(-a0));
    float fg = 1.f / (1.f + expf(-a1));
    float og = 1.f / (1.f + expf(-a2));
    float gg = tanhf(a3);
    float c = fg * g_c[idx] + ig * gg;
    g_c[idx] = c;
    float hn = og * tanhf(c);
    g_h[idx] = hn;
    out[(n * TT + t) * HH + j] = hn;
    bf hi, lo; split2(hn, hi, lo);
    g_hhi[idx] = hi;
    g_hlo[idx] = lo;
}

// ---------------- launch ----------------
extern "C" void kernel_launch(void* const* d_in, const int* in_sizes, int n_in,
                              void* d_out, int out_size) {
    (void)in_sizes; (void)n_in; (void)out_size;
    const float* x     = (const float*)d_in[0];
    const float* A     = (const float*)d_in[1];
    const float* Wx    = (const float*)d_in[2];
    const float* Wh    = (const float*)d_in[3];
    const float* Wattn = (const float*)d_in[4];
    const float* bvec  = (const float*)d_in[5];
    float* out = (float*)d_out;

    const int smemBytes = 8 * SMS * (int)sizeof(bf);   // 81920
    cudaFuncSetAttribute(k_gemm, cudaFuncAttributeMaxDynamicSharedMemorySize, smemBytes);

    k_prepX<<<(TT * NB * DD) / 256, 256>>>(x);
    k_prepW<<<dim3(K3 / 32, N4 / 32), dim3(32, 8)>>>(Wx, Wh, Wattn);
    k_init<<<(NB * HH) / 256, 256>>>(A);

    for (int t = 0; t < TT; ++t) {
        k_att<<<NB, 256>>>(A);
        k_gemm<<<dim3(2, 32, 2), 256, smemBytes>>>(t);
        k_gates<<<(NB * HH) / 256, 256>>>(bvec, out, t);
    }
}

// round 3
// speedup vs baseline: 1.2475x; 1.2475x over previous
#include <cuda_runtime.h>
#include <cuda_bf16.h>
#include <cstdint>

#define NB 256
#define TT 128
#define DD 1024
#define HH 1024
#define LL 49
#define K3 3072
#define N4 4096

typedef __nv_bfloat16 bf;

// ---------------- scratch (static device globals; no runtime allocation) ----------------
__device__ __align__(256) bf    g_Xhi[TT * NB * DD];   // x split hi, layout [t][n][k]
__device__ __align__(256) bf    g_Xlo[TT * NB * DD];   // x split lo
__device__ __align__(256) bf    g_Whi[N4 * K3];        // W concat transposed [n][k], hi
__device__ __align__(256) bf    g_Wlo[N4 * K3];        // lo
__device__ __align__(256) float g_h[NB * HH];
__device__ __align__(256) float g_c[NB * HH];
__device__ __align__(256) bf    g_hhi[NB * HH];
__device__ __align__(256) bf    g_hlo[NB * HH];
__device__ __align__(256) bf    g_ahi[NB * HH];        // attn split
__device__ __align__(256) bf    g_alo[NB * HH];
__device__ __align__(256) float g_P0[NB * N4];         // split-K partial 0
__device__ __align__(256) float g_P1[NB * N4];         // split-K partial 1

__device__ __forceinline__ void split2(float v, bf& hi, bf& lo) {
    hi = __float2bfloat16(v);
    lo = __float2bfloat16(v - __bfloat162float(hi));
}

__device__ __forceinline__ void cp16(const void* smem_dst, const void* gsrc) {
    unsigned s = (unsigned)__cvta_generic_to_shared((void*)smem_dst);
    asm volatile("cp.async.cg.shared.global [%0], [%1], 16;\n" :: "r"(s), "l"(gsrc));
}

__device__ __forceinline__ void mma16816(float* d, const unsigned* a, const unsigned* b) {
    asm volatile(
        "mma.sync.aligned.m16n8k16.row.col.f32.bf16.bf16.f32 "
        "{%0,%1,%2,%3}, {%4,%5,%6,%7}, {%8,%9}, {%0,%1,%2,%3};\n"
        : "+f"(d[0]), "+f"(d[1]), "+f"(d[2]), "+f"(d[3])
        : "r"(a[0]), "r"(a[1]), "r"(a[2]), "r"(a[3]), "r"(b[0]), "r"(b[1]));
}

// ---------------- prep: split x into [t][n][k] bf16 hi/lo ----------------
__global__ void __launch_bounds__(256) k_prepX(const float* __restrict__ x) {
    int idx = blockIdx.x * 256 + threadIdx.x;     // over T*N*D, x is (N,T,D)
    int k = idx & 1023;
    int r = idx >> 10;                            // n*TT + t
    int t = r & 127;
    int n = r >> 7;
    float v = x[idx];
    bf hi, lo; split2(v, hi, lo);
    int o = (t * NB + n) * DD + k;
    g_Xhi[o] = hi;
    g_Xlo[o] = lo;
}

// ---------------- prep: transpose + split weights into [n][k] concat ----------------
__global__ void k_prepW(const float* __restrict__ Wx, const float* __restrict__ Wh,
                        const float* __restrict__ Wattn) {
    __shared__ float tile[32][33];
    int k0 = blockIdx.x * 32, n0 = blockIdx.y * 32;
    int tx = threadIdx.x, ty = threadIdx.y;       // block (32,8)
    const float* src; int kb;
    if (k0 < 1024)      { src = Wx;    kb = 0; }
    else if (k0 < 2048) { src = Wh;    kb = 1024; }
    else                { src = Wattn; kb = 2048; }
    #pragma unroll
    for (int i = 0; i < 4; ++i) {
        int r = ty + i * 8;
        tile[r][tx] = src[(k0 - kb + r) * N4 + n0 + tx];
    }
    __syncthreads();
    #pragma unroll
    for (int i = 0; i < 4; ++i) {
        int r = ty + i * 8;
        int n = n0 + r, k = k0 + tx;
        float v = tile[tx][r];
        bf hi, lo; split2(v, hi, lo);
        g_Whi[n * K3 + k] = hi;
        g_Wlo[n * K3 + k] = lo;
    }
}

// ---------------- prep: h0 = c0 = mean over spatial dims of A ----------------
__global__ void __launch_bounds__(256) k_init(const float* __restrict__ A) {
    int idx = blockIdx.x * 256 + threadIdx.x;     // over NB*HH
    const float* Ap = A + (size_t)idx * LL;
    float s = 0.f;
    #pragma unroll
    for (int l = 0; l < LL; ++l) s += Ap[l];
    s *= (1.f / 49.f);
    g_h[idx] = s;
    g_c[idx] = s;
    bf hi, lo; split2(s, hi, lo);
    g_hhi[idx] = hi;
    g_hlo[idx] = lo;
}

// ---------------- per-step attention: A slice SMEM-resident, read once ----------------
// grid NB, block 512, dynamic smem = HH*LL*4 = 200704 B
__global__ void __launch_bounds__(512) k_att(const float* __restrict__ A) {
    const int n = blockIdx.x;
    const int tid = threadIdx.x;
    const int lane = tid & 31, wid = tid >> 5;
    extern __shared__ float sA[];                 // [HH][LL]
    __shared__ float sh[HH];
    __shared__ float sw[64];

    // stream A slice into smem (once), h vector alongside
    {
        const float4* Ap = (const float4*)(A + (size_t)n * (HH * LL));
        float4* dst = (float4*)sA;
        #pragma unroll 4
        for (int i = tid; i < (HH * LL) / 4; i += 512)
            cp16(dst + i, Ap + i);
        asm volatile("cp.async.commit_group;\n" ::);
        for (int i = tid; i < HH; i += 512) sh[i] = g_h[n * HH + i];
        asm volatile("cp.async.wait_group 0;\n" ::);
    }
    __syncthreads();

    // pass 1: scores[l] = sum_h A[h][l] * h[h]   (warp per l; stride-49 is conflict-free)
    for (int l = wid; l < LL; l += 16) {
        float acc = 0.f;
        #pragma unroll 8
        for (int h = lane; h < HH; h += 32)
            acc += sA[h * LL + l] * sh[h];
        #pragma unroll
        for (int off = 16; off; off >>= 1)
            acc += __shfl_xor_sync(0xffffffffu, acc, off);
        if (lane == 0) sw[l] = acc * 0.03125f;    // 1/sqrt(H)
    }
    __syncthreads();

    // softmax over 49 scores (warp 0, butterfly)
    if (wid == 0) {
        float v0 = (lane < LL) ? sw[lane] : -1e30f;
        float v1 = (lane + 32 < LL) ? sw[lane + 32] : -1e30f;
        float m = fmaxf(v0, v1);
        #pragma unroll
        for (int off = 16; off; off >>= 1)
            m = fmaxf(m, __shfl_xor_sync(0xffffffffu, m, off));
        float e0 = (lane < LL) ? __expf(v0 - m) : 0.f;
        float e1 = (lane + 32 < LL) ? __expf(v1 - m) : 0.f;
        float s = e0 + e1;
        #pragma unroll
        for (int off = 16; off; off >>= 1)
            s += __shfl_xor_sync(0xffffffffu, s, off);
        float inv = 1.f / s;
        if (lane < LL) sw[lane] = e0 * inv;
        if (lane + 32 < LL) sw[lane + 32] = e1 * inv;
    }
    __syncthreads();

    // pass 2: attn[h] = sum_l w[l] * A[h][l]   (from smem, conflict-free)
    for (int h = tid; h < HH; h += 512) {
        const float* row = sA + h * LL;
        float acc = 0.f;
        #pragma unroll
        for (int l = 0; l < LL; ++l) acc += sw[l] * row[l];
        bf hi, lo; split2(acc, hi, lo);
        g_ahi[n * HH + h] = hi;
        g_alo[n * HH + h] = lo;
    }
}

// ---------------- per-step GEMM: [x_t | h | attn](256x3072) @ W^T(3072x4096), split-K=2 ----------------
// bf16 2-way split (hi/lo): C = Ah*Bh + Ah*Bl + Al*Bh  (fp32 accumulate)
// 3-stage cp.async pipeline, wait_group 1
#define SMS 5120   // 128*40 bf16 per stage per matrix
#define NSTAGE 3

__device__ __forceinline__ void gemm_load_chunk(int t, int kc, int buf, int bm, int bn, int tid,
                                                bf* sAh, bf* sAl, bf* sBh, bf* sBl) {
    const bf *pAh, *pAl; int kb;
    if (kc < 1024)      { int o = t * (NB * DD); pAh = g_Xhi + o; pAl = g_Xlo + o; kb = 0; }
    else if (kc < 2048) { pAh = g_hhi; pAl = g_hlo; kb = 1024; }
    else                { pAh = g_ahi; pAl = g_alo; kb = 2048; }
    const int kA = kc - kb;
    #pragma unroll
    for (int j = 0; j < 2; ++j) {
        int v = tid + 256 * j;
        int row = v >> 2, cq = v & 3;
        int soff = buf * SMS + row * 40 + cq * 8;
        int gA = (bm * 128 + row) * 1024 + kA + cq * 8;
        int gB = (bn * 128 + row) * K3 + kc + cq * 8;
        cp16(sAh + soff, pAh + gA);
        cp16(sAl + soff, pAl + gA);
        cp16(sBh + soff, g_Whi + gB);
        cp16(sBl + soff, g_Wlo + gB);
    }
    asm volatile("cp.async.commit_group;\n" ::);
}

__global__ void __launch_bounds__(256, 1) k_gemm(int t) {
    const int bm = blockIdx.x;   // 0..1
    const int bn = blockIdx.y;   // 0..31
    const int z  = blockIdx.z;   // 0..1 split-K
    extern __shared__ bf sm[];
    bf* sAh = sm;
    bf* sAl = sm + NSTAGE * SMS;
    bf* sBh = sm + 2 * NSTAGE * SMS;
    bf* sBl = sm + 3 * NSTAGE * SMS;
    const int tid  = threadIdx.x;
    const int lane = tid & 31, w = tid >> 5;
    const int wm = w & 1, wn = w >> 1;          // 2x4 warp grid, warp tile 64x32
    const int lr = lane >> 2, lc = lane & 3;

    float d[4][4][4];
    #pragma unroll
    for (int a = 0; a < 4; ++a)
        #pragma unroll
        for (int b2 = 0; b2 < 4; ++b2)
            #pragma unroll
            for (int c = 0; c < 4; ++c) d[a][b2][c] = 0.f;

    const int kc0 = z * 1536;
    gemm_load_chunk(t, kc0, 0, bm, bn, tid, sAh, sAl, sBh, sBl);
    gemm_load_chunk(t, kc0 + 32, 1, bm, bn, tid, sAh, sAl, sBh, sBl);

    int cb = 0;   // compute buffer
    int lb = 2;   // next load buffer
    for (int it = 0; it < 48; ++it) {
        asm volatile("cp.async.wait_group 1;\n" ::);
        __syncthreads();
        if (it + 2 < 48) {
            gemm_load_chunk(t, kc0 + (it + 2) * 32, lb, bm, bn, tid, sAh, sAl, sBh, sBl);
            if (++lb == NSTAGE) lb = 0;
        }
        const bf* Ah = sAh + cb * SMS;
        const bf* Al = sAl + cb * SMS;
        const bf* Bh = sBh + cb * SMS;
        const bf* Bl = sBl + cb * SMS;
        if (++cb == NSTAGE) cb = 0;
        #pragma unroll
        for (int kt = 0; kt < 32; kt += 16) {
            unsigned ah[4][4], al[4][4], bh[4][2], bl[4][2];
            #pragma unroll
            for (int mt = 0; mt < 4; ++mt) {
                int r0 = wm * 64 + mt * 16 + lr;
                int c0 = kt + lc * 2;
                ah[mt][0] = *(const unsigned*)(Ah + r0 * 40 + c0);
                ah[mt][1] = *(const unsigned*)(Ah + (r0 + 8) * 40 + c0);
                ah[mt][2] = *(const unsigned*)(Ah + r0 * 40 + c0 + 8);
                ah[mt][3] = *(const unsigned*)(Ah + (r0 + 8) * 40 + c0 + 8);
                al[mt][0] = *(const unsigned*)(Al + r0 * 40 + c0);
                al[mt][1] = *(const unsigned*)(Al + (r0 + 8) * 40 + c0);
                al[mt][2] = *(const unsigned*)(Al + r0 * 40 + c0 + 8);
                al[mt][3] = *(const unsigned*)(Al + (r0 + 8) * 40 + c0 + 8);
            }
            #pragma unroll
            for (int nt = 0; nt < 4; ++nt) {
                int rB = wn * 32 + nt * 8 + lr;
                int cB = kt + lc * 2;
                bh[nt][0] = *(const unsigned*)(Bh + rB * 40 + cB);
                bh[nt][1] = *(const unsigned*)(Bh + rB * 40 + cB + 8);
                bl[nt][0] = *(const unsigned*)(Bl + rB * 40 + cB);
                bl[nt][1] = *(const unsigned*)(Bl + rB * 40 + cB + 8);
            }
            #pragma unroll
            for (int mt = 0; mt < 4; ++mt)
                #pragma unroll
                for (int nt = 0; nt < 4; ++nt) {
                    mma16816(d[mt][nt], ah[mt], bh[nt]);
                    mma16816(d[mt][nt], ah[mt], bl[nt]);
                    mma16816(d[mt][nt], al[mt], bh[nt]);
                }
        }
        __syncthreads();
    }

    float* P = z ? g_P1 : g_P0;
    #pragma unroll
    for (int mt = 0; mt < 4; ++mt) {
        int r = bm * 128 + wm * 64 + mt * 16 + lr;
        #pragma unroll
        for (int nt = 0; nt < 4; ++nt) {
            int cN = bn * 128 + wn * 32 + nt * 8 + 2 * lc;
            float2 v0 = make_float2(d[mt][nt][0], d[mt][nt][1]);
            float2 v1 = make_float2(d[mt][nt][2], d[mt][nt][3]);
            *(float2*)&P[r * N4 + cN]       = v0;
            *(float2*)&P[(r + 8) * N4 + cN] = v1;
        }
    }
}

// ---------------- per-step gates + state update + output + h split ----------------
__global__ void __launch_bounds__(256) k_gates(const float* __restrict__ bvec,
                                               float* __restrict__ out, int t) {
    int idx = blockIdx.x * 256 + threadIdx.x;    // over NB*HH
    int n = idx >> 10, j = idx & 1023;
    int base = n * N4 + j;
    float a0 = g_P0[base]          + g_P1[base]          + bvec[j];
    float a1 = g_P0[base + 1024]   + g_P1[base + 1024]   + bvec[j + 1024];
    float a2 = g_P0[base + 2048]   + g_P1[base + 2048]   + bvec[j + 2048];
    float a3 = g_P0[base + 3072]   + g_P1[base + 3072]   + bvec[j + 3072];
    float ig = 1.f / (1.f + expf(-a0));
    float fg = 1.f / (1.f + expf(-a1));
    float og = 1.f / (1.f + expf(-a2));
    float gg = tanhf(a3);
    float c = fg * g_c[idx] + ig * gg;
    g_c[idx] = c;
    float hn = og * tanhf(c);
    g_h[idx] = hn;
    out[(n * TT + t) * HH + j] = hn;
    bf hi, lo; split2(hn, hi, lo);
    g_hhi[idx] = hi;
    g_hlo[idx] = lo;
}

// ---------------- launch ----------------
extern "C" void kernel_launch(void* const* d_in, const int* in_sizes, int n_in,
                              void* d_out, int out_size) {
    (void)in_sizes; (void)n_in; (void)out_size;
    const float* x     = (const float*)d_in[0];
    const float* A     = (const float*)d_in[1];
    const float* Wx    = (const float*)d_in[2];
    const float* Wh    = (const float*)d_in[3];
    const float* Wattn = (const float*)d_in[4];
    const float* bvec  = (const float*)d_in[5];
    float* out = (float*)d_out;

    const int gemmSmem = 4 * NSTAGE * SMS * (int)sizeof(bf);   // 122880
    const int attSmem  = HH * LL * (int)sizeof(float);         // 200704
    cudaFuncSetAttribute(k_gemm, cudaFuncAttributeMaxDynamicSharedMemorySize, gemmSmem);
    cudaFuncSetAttribute(k_att,  cudaFuncAttributeMaxDynamicSharedMemorySize, attSmem);

    k_prepX<<<(TT * NB * DD) / 256, 256>>>(x);
    k_prepW<<<dim3(K3 / 32, N4 / 32), dim3(32, 8)>>>(Wx, Wh, Wattn);
    k_init<<<(NB * HH) / 256, 256>>>(A);

    for (int t = 0; t < TT; ++t) {
        k_att<<<NB, 512, attSmem>>>(A);
        k_gemm<<<dim3(2, 32, 2), 256, gemmSmem>>>(t);
        k_gates<<<(NB * HH) / 256, 256>>>(bvec, out, t);
    }
}

// round 5
// speedup vs baseline: 1.2830x; 1.0284x over previous
#include <cuda_runtime.h>
#include <cuda_bf16.h>
#include <cstdint>

#define NB 256
#define TT 128
#define DD 1024
#define HH 1024
#define LL 49
#define K3 3072
#define N4 4096

typedef __nv_bfloat16 bf;

// ---------------- scratch (static device globals; no runtime allocation) ----------------
__device__ __align__(256) bf    g_Xhi[TT * NB * DD];   // x split hi, layout [t][n][k]
__device__ __align__(256) bf    g_Xlo[TT * NB * DD];   // x split lo
__device__ __align__(256) bf    g_Whi[N4 * K3];        // W concat transposed [n][k], hi
__device__ __align__(256) bf    g_Wlo[N4 * K3];        // lo
__device__ __align__(256) float g_h[NB * HH];
__device__ __align__(256) float g_c[NB * HH];
__device__ __align__(256) bf    g_hhi[NB * HH];
__device__ __align__(256) bf    g_hlo[NB * HH];
__device__ __align__(256) bf    g_ahi[NB * HH];        // attn split
__device__ __align__(256) bf    g_alo[NB * HH];
__device__ __align__(256) float g_P0[NB * N4];         // split-K partial 0
__device__ __align__(256) float g_P1[NB * N4];         // split-K partial 1

__device__ __forceinline__ void split2(float v, bf& hi, bf& lo) {
    hi = __float2bfloat16(v);
    lo = __float2bfloat16(v - __bfloat162float(hi));
}

__device__ __forceinline__ void cp16(const void* smem_dst, const void* gsrc) {
    unsigned s = (unsigned)__cvta_generic_to_shared((void*)smem_dst);
    asm volatile("cp.async.cg.shared.global [%0], [%1], 16;\n" :: "r"(s), "l"(gsrc));
}

__device__ __forceinline__ void mma16816(float* d, const unsigned* a, const unsigned* b) {
    asm volatile(
        "mma.sync.aligned.m16n8k16.row.col.f32.bf16.bf16.f32 "
        "{%0,%1,%2,%3}, {%4,%5,%6,%7}, {%8,%9}, {%0,%1,%2,%3};\n"
        : "+f"(d[0]), "+f"(d[1]), "+f"(d[2]), "+f"(d[3])
        : "r"(a[0]), "r"(a[1]), "r"(a[2]), "r"(a[3]), "r"(b[0]), "r"(b[1]));
}

__device__ __forceinline__ void ldsm_x4(unsigned* r, unsigned addr) {
    asm volatile("ldmatrix.sync.aligned.m8n8.x4.shared.b16 {%0,%1,%2,%3}, [%4];"
                 : "=r"(r[0]), "=r"(r[1]), "=r"(r[2]), "=r"(r[3]) : "r"(addr));
}
__device__ __forceinline__ void ldsm_x2(unsigned* r, unsigned addr) {
    asm volatile("ldmatrix.sync.aligned.m8n8.x2.shared.b16 {%0,%1}, [%2];"
                 : "=r"(r[0]), "=r"(r[1]) : "r"(addr));
}

// ---------------- prep: split x into [t][n][k] bf16 hi/lo ----------------
__global__ void __launch_bounds__(256) k_prepX(const float* __restrict__ x) {
    int idx = blockIdx.x * 256 + threadIdx.x;     // over T*N*D, x is (N,T,D)
    int k = idx & 1023;
    int r = idx >> 10;                            // n*TT + t
    int t = r & 127;
    int n = r >> 7;
    float v = x[idx];
    bf hi, lo; split2(v, hi, lo);
    int o = (t * NB + n) * DD + k;
    g_Xhi[o] = hi;
    g_Xlo[o] = lo;
}

// ---------------- prep: transpose + split weights into [n][k] concat ----------------
__global__ void k_prepW(const float* __restrict__ Wx, const float* __restrict__ Wh,
                        const float* __restrict__ Wattn) {
    __shared__ float tile[32][33];
    int k0 = blockIdx.x * 32, n0 = blockIdx.y * 32;
    int tx = threadIdx.x, ty = threadIdx.y;       // block (32,8)
    const float* src; int kb;
    if (k0 < 1024)      { src = Wx;    kb = 0; }
    else if (k0 < 2048) { src = Wh;    kb = 1024; }
    else                { src = Wattn; kb = 2048; }
    #pragma unroll
    for (int i = 0; i < 4; ++i) {
        int r = ty + i * 8;
        tile[r][tx] = src[(k0 - kb + r) * N4 + n0 + tx];
    }
    __syncthreads();
    #pragma unroll
    for (int i = 0; i < 4; ++i) {
        int r = ty + i * 8;
        int n = n0 + r, k = k0 + tx;
        float v = tile[tx][r];
        bf hi, lo; split2(v, hi, lo);
        g_Whi[n * K3 + k] = hi;
        g_Wlo[n * K3 + k] = lo;
    }
}

// ---------------- prep: h0 = c0 = mean over spatial dims of A ----------------
__global__ void __launch_bounds__(256) k_init(const float* __restrict__ A) {
    int idx = blockIdx.x * 256 + threadIdx.x;     // over NB*HH
    const float* Ap = A + (size_t)idx * LL;
    float s = 0.f;
    #pragma unroll
    for (int l = 0; l < LL; ++l) s += Ap[l];
    s *= (1.f / 49.f);
    g_h[idx] = s;
    g_c[idx] = s;
    bf hi, lo; split2(s, hi, lo);
    g_hhi[idx] = hi;
    g_hlo[idx] = lo;
}

// ---------------- per-step attention: A slice SMEM-resident, read once ----------------
// grid NB, block 1024, dynamic smem = HH*LL*4 = 200704 B
__global__ void __launch_bounds__(1024) k_att(const float* __restrict__ A) {
    const int n = blockIdx.x;
    const int tid = threadIdx.x;
    const int lane = tid & 31, wid = tid >> 5;
    extern __shared__ float sA[];                 // [HH][LL]
    __shared__ float sh[HH];
    __shared__ float sw[64];

    {
        const float4* Ap = (const float4*)(A + (size_t)n * (HH * LL));
        float4* dst = (float4*)sA;
        #pragma unroll 4
        for (int i = tid; i < (HH * LL) / 4; i += 1024)
            cp16(dst + i, Ap + i);
        asm volatile("cp.async.commit_group;\n" ::);
        if (tid < HH) sh[tid] = g_h[n * HH + tid];
        asm volatile("cp.async.wait_group 0;\n" ::);
    }
    __syncthreads();

    // pass 1: scores[l] = sum_h A[h][l] * h[h]   (warp per l; stride-49 conflict-free)
    for (int l = wid; l < LL; l += 32) {
        float acc = 0.f;
        #pragma unroll 8
        for (int h = lane; h < HH; h += 32)
            acc += sA[h * LL + l] * sh[h];
        #pragma unroll
        for (int off = 16; off; off >>= 1)
            acc += __shfl_xor_sync(0xffffffffu, acc, off);
        if (lane == 0) sw[l] = acc * 0.03125f;    // 1/sqrt(H)
    }
    __syncthreads();

    // softmax over 49 scores (warp 0, butterfly)
    if (wid == 0) {
        float v0 = (lane < LL) ? sw[lane] : -1e30f;
        float v1 = (lane + 32 < LL) ? sw[lane + 32] : -1e30f;
        float m = fmaxf(v0, v1);
        #pragma unroll
        for (int off = 16; off; off >>= 1)
            m = fmaxf(m, __shfl_xor_sync(0xffffffffu, m, off));
        float e0 = (lane < LL) ? __expf(v0 - m) : 0.f;
        float e1 = (lane + 32 < LL) ? __expf(v1 - m) : 0.f;
        float s = e0 + e1;
        #pragma unroll
        for (int off = 16; off; off >>= 1)
            s += __shfl_xor_sync(0xffffffffu, s, off);
        float inv = 1.f / s;
        if (lane < LL) sw[lane] = e0 * inv;
        if (lane + 32 < LL) sw[lane + 32] = e1 * inv;
    }
    __syncthreads();

    // pass 2: attn[h] = sum_l w[l] * A[h][l]
    for (int h = tid; h < HH; h += 1024) {
        const float* row = sA + h * LL;
        float acc = 0.f;
        #pragma unroll
        for (int l = 0; l < LL; ++l) acc += sw[l] * row[l];
        bf hi, lo; split2(acc, hi, lo);
        g_ahi[n * HH + h] = hi;
        g_alo[n * HH + h] = lo;
    }
}

// ---------------- per-step GEMM: [x_t | h | attn](256x3072) @ W^T(3072x4096), split-K=2 ----------------
// bf16 2-way split (hi/lo): C = Ah*Bh + Ah*Bl + Al*Bh  (fp32 accumulate)
// 3-stage cp.async pipeline, ldmatrix fragment loads
#define SMS 5120   // 128*40 bf16 per stage per matrix
#define NSTAGE 3

__device__ __forceinline__ void gemm_load_chunk(int t, int kc, int buf, int bm, int bn, int tid,
                                                bf* sAh, bf* sAl, bf* sBh, bf* sBl) {
    const bf *pAh, *pAl; int kb;
    if (kc < 1024)      { int o = t * (NB * DD); pAh = g_Xhi + o; pAl = g_Xlo + o; kb = 0; }
    else if (kc < 2048) { pAh = g_hhi; pAl = g_hlo; kb = 1024; }
    else                { pAh = g_ahi; pAl = g_alo; kb = 2048; }
    const int kA = kc - kb;
    #pragma unroll
    for (int j = 0; j < 2; ++j) {
        int v = tid + 256 * j;
        int row = v >> 2, cq = v & 3;
        int soff = buf * SMS + row * 40 + cq * 8;
        int gA = (bm * 128 + row) * 1024 + kA + cq * 8;
        int gB = (bn * 128 + row) * K3 + kc + cq * 8;
        cp16(sAh + soff, pAh + gA);
        cp16(sAl + soff, pAl + gA);
        cp16(sBh + soff, g_Whi + gB);
        cp16(sBl + soff, g_Wlo + gB);
    }
    asm volatile("cp.async.commit_group;\n" ::);
}

__global__ void __launch_bounds__(256, 1) k_gemm(int t) {
    const int bm = blockIdx.x;   // 0..1
    const int bn = blockIdx.y;   // 0..31
    const int z  = blockIdx.z;   // 0..1 split-K
    extern __shared__ bf sm[];
    bf* sAh = sm;
    bf* sAl = sm + NSTAGE * SMS;
    bf* sBh = sm + 2 * NSTAGE * SMS;
    bf* sBl = sm + 3 * NSTAGE * SMS;
    const int tid  = threadIdx.x;
    const int lane = tid & 31, w = tid >> 5;
    const int wm = w & 1, wn = w >> 1;          // 2x4 warp grid, warp tile 64x32
    const int lr = lane >> 2, lc = lane & 3;

    // smem byte bases for ldmatrix
    const unsigned bAh = (unsigned)__cvta_generic_to_shared(sAh);
    const unsigned bAl = (unsigned)__cvta_generic_to_shared(sAl);
    const unsigned bBh = (unsigned)__cvta_generic_to_shared(sBh);
    const unsigned bBl = (unsigned)__cvta_generic_to_shared(sBl);
    // per-lane ldmatrix row offsets (bytes); row stride = 40 bf16 = 80 B
    const unsigned aoff = (unsigned)((wm * 64 + (lane & 7) + ((lane >> 3) & 1) * 8) * 80
                                     + ((lane >> 4) & 1) * 16);
    const unsigned boff = (unsigned)((wn * 32 + (lane & 7)) * 80 + ((lane >> 3) & 1) * 16);

    float d[4][4][4];
    #pragma unroll
    for (int a = 0; a < 4; ++a)
        #pragma unroll
        for (int b2 = 0; b2 < 4; ++b2)
            #pragma unroll
            for (int c = 0; c < 4; ++c) d[a][b2][c] = 0.f;

    const int kc0 = z * 1536;
    gemm_load_chunk(t, kc0, 0, bm, bn, tid, sAh, sAl, sBh, sBl);
    gemm_load_chunk(t, kc0 + 32, 1, bm, bn, tid, sAh, sAl, sBh, sBl);

    int cb = 0;   // compute buffer
    int lb = 2;   // next load buffer
    for (int it = 0; it < 48; ++it) {
        asm volatile("cp.async.wait_group 1;\n" ::);
        __syncthreads();
        if (it + 2 < 48) {
            gemm_load_chunk(t, kc0 + (it + 2) * 32, lb, bm, bn, tid, sAh, sAl, sBh, sBl);
            if (++lb == NSTAGE) lb = 0;
        }
        const unsigned cbo = (unsigned)(cb * SMS * 2);
        if (++cb == NSTAGE) cb = 0;
        #pragma unroll
        for (int kt = 0; kt < 32; kt += 16) {
            unsigned ah[4][4], al[4][4], bh[4][2], bl[4][2];
            #pragma unroll
            for (int mt = 0; mt < 4; ++mt) {
                unsigned o = cbo + (unsigned)(mt * 1280 + kt * 2) + aoff;
                ldsm_x4(ah[mt], bAh + o);
                ldsm_x4(al[mt], bAl + o);
            }
            #pragma unroll
            for (int nt = 0; nt < 4; ++nt) {
                unsigned o = cbo + (unsigned)(nt * 640 + kt * 2) + boff;
                ldsm_x2(bh[nt], bBh + o);
                ldsm_x2(bl[nt], bBl + o);
            }
            #pragma unroll
            for (int mt = 0; mt < 4; ++mt)
                #pragma unroll
                for (int nt = 0; nt < 4; ++nt) {
                    mma16816(d[mt][nt], ah[mt], bh[nt]);
                    mma16816(d[mt][nt], ah[mt], bl[nt]);
                    mma16816(d[mt][nt], al[mt], bh[nt]);
                }
        }
        __syncthreads();
    }

    float* P = z ? g_P1 : g_P0;
    #pragma unroll
    for (int mt = 0; mt < 4; ++mt) {
        int r = bm * 128 + wm * 64 + mt * 16 + lr;
        #pragma unroll
        for (int nt = 0; nt < 4; ++nt) {
            int cN = bn * 128 + wn * 32 + nt * 8 + 2 * lc;
            float2 v0 = make_float2(d[mt][nt][0], d[mt][nt][1]);
            float2 v1 = make_float2(d[mt][nt][2], d[mt][nt][3]);
            *(float2*)&P[r * N4 + cN]       = v0;
            *(float2*)&P[(r + 8) * N4 + cN] = v1;
        }
    }
}

// ---------------- per-step gates + state update + output + h split ----------------
__global__ void __launch_bounds__(256) k_gates(const float* __restrict__ bvec,
                                               float* __restrict__ out, int t) {
    int idx = blockIdx.x * 256 + threadIdx.x;    // over NB*HH
    int n = idx >> 10, j = idx & 1023;
    int base = n * N4 + j;
    float a0 = g_P0[base]          + g_P1[base]          + bvec[j];
    float a1 = g_P0[base + 1024]   + g_P1[base + 1024]   + bvec[j + 1024];
    float a2 = g_P0[base + 2048]   + g_P1[base + 2048]   + bvec[j + 2048];
    float a3 = g_P0[base + 3072]   + g_P1[base + 3072]   + bvec[j + 3072];
    float ig = 1.f / (1.f + expf(-a0));
    float fg = 1.f / (1.f + expf(-a1));
    float og = 1.f / (1.f + expf(-a2));
    float gg = tanhf(a3);
    float c = fg * g_c[idx] + ig * gg;
    g_c[idx] = c;
    float hn = og * tanhf(c);
    g_h[idx] = hn;
    out[(n * TT + t) * HH + j] = hn;
    bf hi, lo; split2(hn, hi, lo);
    g_hhi[idx] = hi;
    g_hlo[idx] = lo;
}

// ---------------- launch ----------------
extern "C" void kernel_launch(void* const* d_in, const int* in_sizes, int n_in,
                              void* d_out, int out_size) {
    (void)in_sizes; (void)n_in; (void)out_size;
    const float* x     = (const float*)d_in[0];
    const float* A     = (const float*)d_in[1];
    const float* Wx    = (const float*)d_in[2];
    const float* Wh    = (const float*)d_in[3];
    const float* Wattn = (const float*)d_in[4];
    const float* bvec  = (const float*)d_in[5];
    float* out = (float*)d_out;

    const int gemmSmem = 4 * NSTAGE * SMS * (int)sizeof(bf);   // 122880
    const int attSmem  = HH * LL * (int)sizeof(float);         // 200704
    cudaFuncSetAttribute(k_gemm, cudaFuncAttributeMaxDynamicSharedMemorySize, gemmSmem);
    cudaFuncSetAttribute(k_att,  cudaFuncAttributeMaxDynamicSharedMemorySize, attSmem);

    k_prepX<<<(TT * NB * DD) / 256, 256>>>(x);
    k_prepW<<<dim3(K3 / 32, N4 / 32), dim3(32, 8)>>>(Wx, Wh, Wattn);
    k_init<<<(NB * HH) / 256, 256>>>(A);

    for (int t = 0; t < TT; ++t) {
        k_att<<<NB, 1024, attSmem>>>(A);
        k_gemm<<<dim3(2, 32, 2), 256, gemmSmem>>>(t);
        k_gates<<<(NB * HH) / 256, 256>>>(bvec, out, t);
    }
}

// round 7
// speedup vs baseline: 1.5767x; 1.2290x over previous
#include <cuda_runtime.h>
#include <cuda_fp16.h>
#include <cstdint>

#define NB 256
#define TT 128
#define DD 1024
#define HH 1024
#define LL 49
#define K3 3072
#define N4 4096

typedef __half hf;

// ---------------- scratch (static device globals; no runtime allocation) ----------------
__device__ __align__(256) hf    g_X16[TT * NB * DD];   // x fp16, layout [t][n][k]
__device__ __align__(256) hf    g_Wh16[N4 * K3];       // W concat transposed [n][k], fp16 hi
__device__ __align__(256) hf    g_Wl16[N4 * K3];       // fp16 lo (W - hi)
__device__ __align__(256) float g_h[NB * HH];
__device__ __align__(256) float g_c[NB * HH];
__device__ __align__(256) hf    g_h16[NB * HH];
__device__ __align__(256) hf    g_a16[NB * HH];        // attn fp16
__device__ __align__(256) float g_P0[NB * N4];         // split-K partial 0
__device__ __align__(256) float g_P1[NB * N4];         // split-K partial 1

__device__ __forceinline__ void cp16(const void* smem_dst, const void* gsrc) {
    unsigned s = (unsigned)__cvta_generic_to_shared((void*)smem_dst);
    asm volatile("cp.async.cg.shared.global [%0], [%1], 16;\n" :: "r"(s), "l"(gsrc));
}
__device__ __forceinline__ void cp16_ll(const void* smem_dst, const void* gsrc, uint64_t pol) {
    unsigned s = (unsigned)__cvta_generic_to_shared((void*)smem_dst);
    asm volatile("cp.async.cg.shared.global.L2::cache_hint [%0], [%1], 16, %2;\n"
                 :: "r"(s), "l"(gsrc), "l"(pol));
}
__device__ __forceinline__ uint64_t mkpol_evict_last() {
    uint64_t pol;
    asm("createpolicy.fractional.L2::evict_last.b64 %0, 1.0;" : "=l"(pol));
    return pol;
}

__device__ __forceinline__ void mma16816(float* d, const unsigned* a, const unsigned* b) {
    asm volatile(
        "mma.sync.aligned.m16n8k16.row.col.f32.f16.f16.f32 "
        "{%0,%1,%2,%3}, {%4,%5,%6,%7}, {%8,%9}, {%0,%1,%2,%3};\n"
        : "+f"(d[0]), "+f"(d[1]), "+f"(d[2]), "+f"(d[3])
        : "r"(a[0]), "r"(a[1]), "r"(a[2]), "r"(a[3]), "r"(b[0]), "r"(b[1]));
}

__device__ __forceinline__ void ldsm_x4(unsigned* r, unsigned addr) {
    asm volatile("ldmatrix.sync.aligned.m8n8.x4.shared.b16 {%0,%1,%2,%3}, [%4];"
                 : "=r"(r[0]), "=r"(r[1]), "=r"(r[2]), "=r"(r[3]) : "r"(addr));
}
__device__ __forceinline__ void ldsm_x2(unsigned* r, unsigned addr) {
    asm volatile("ldmatrix.sync.aligned.m8n8.x2.shared.b16 {%0,%1}, [%2];"
                 : "=r"(r[0]), "=r"(r[1]) : "r"(addr));
}

// ---------------- prep: x -> fp16 [t][n][k] ----------------
__global__ void __launch_bounds__(256) k_prepX(const float* __restrict__ x) {
    int idx = blockIdx.x * 256 + threadIdx.x;     // over T*N*D, x is (N,T,D)
    int k = idx & 1023;
    int r = idx >> 10;                            // n*TT + t
    int t = r & 127;
    int n = r >> 7;
    g_X16[(t * NB + n) * DD + k] = __float2half(x[idx]);
}

// ---------------- prep: transpose + fp16 hi/lo split of weights ----------------
__global__ void k_prepW(const float* __restrict__ Wx, const float* __restrict__ Wh,
                        const float* __restrict__ Wattn) {
    __shared__ float tile[32][33];
    int k0 = blockIdx.x * 32, n0 = blockIdx.y * 32;
    int tx = threadIdx.x, ty = threadIdx.y;       // block (32,8)
    const float* src; int kb;
    if (k0 < 1024)      { src = Wx;    kb = 0; }
    else if (k0 < 2048) { src = Wh;    kb = 1024; }
    else                { src = Wattn; kb = 2048; }
    #pragma unroll
    for (int i = 0; i < 4; ++i) {
        int r = ty + i * 8;
        tile[r][tx] = src[(k0 - kb + r) * N4 + n0 + tx];
    }
    __syncthreads();
    #pragma unroll
    for (int i = 0; i < 4; ++i) {
        int r = ty + i * 8;
        int n = n0 + r, k = k0 + tx;
        float v = tile[tx][r];
        hf hi = __float2half(v);
        hf lo = __float2half(v - __half2float(hi));
        g_Wh16[n * K3 + k] = hi;
        g_Wl16[n * K3 + k] = lo;
    }
}

// ---------------- prep: h0 = c0 = mean over spatial dims of A ----------------
__global__ void __launch_bounds__(256) k_init(const float* __restrict__ A) {
    int idx = blockIdx.x * 256 + threadIdx.x;     // over NB*HH
    const float* Ap = A + (size_t)idx * LL;
    float s = 0.f;
    #pragma unroll
    for (int l = 0; l < LL; ++l) s += Ap[l];
    s *= (1.f / 49.f);
    g_h[idx] = s;
    g_c[idx] = s;
    g_h16[idx] = __float2half(s);
}

// ---------------- per-step attention: A slice SMEM-resident, read once (L2 evict_last) ----------------
// grid NB, block 1024, dynamic smem = HH*LL*4 = 200704 B
__global__ void __launch_bounds__(1024) k_att(const float* __restrict__ A) {
    const int n = blockIdx.x;
    const int tid = threadIdx.x;
    const int lane = tid & 31, wid = tid >> 5;
    extern __shared__ float sA[];                 // [HH][LL]
    __shared__ float sh[HH];
    __shared__ float sw[64];

    {
        const uint64_t pol = mkpol_evict_last();
        const float4* Ap = (const float4*)(A + (size_t)n * (HH * LL));
        float4* dst = (float4*)sA;
        #pragma unroll 4
        for (int i = tid; i < (HH * LL) / 4; i += 1024)
            cp16_ll(dst + i, Ap + i, pol);
        asm volatile("cp.async.commit_group;\n" ::);
        if (tid < HH) sh[tid] = g_h[n * HH + tid];
        asm volatile("cp.async.wait_group 0;\n" ::);
    }
    __syncthreads();

    // pass 1: scores[l] = sum_h A[h][l] * h[h]   (warp per l; stride-49 conflict-free)
    for (int l = wid; l < LL; l += 32) {
        float acc = 0.f;
        #pragma unroll 8
        for (int h = lane; h < HH; h += 32)
            acc += sA[h * LL + l] * sh[h];
        #pragma unroll
        for (int off = 16; off; off >>= 1)
            acc += __shfl_xor_sync(0xffffffffu, acc, off);
        if (lane == 0) sw[l] = acc * 0.03125f;    // 1/sqrt(H)
    }
    __syncthreads();

    // softmax over 49 scores (warp 0, butterfly)
    if (wid == 0) {
        float v0 = (lane < LL) ? sw[lane] : -1e30f;
        float v1 = (lane + 32 < LL) ? sw[lane + 32] : -1e30f;
        float m = fmaxf(v0, v1);
        #pragma unroll
        for (int off = 16; off; off >>= 1)
            m = fmaxf(m, __shfl_xor_sync(0xffffffffu, m, off));
        float e0 = (lane < LL) ? __expf(v0 - m) : 0.f;
        float e1 = (lane + 32 < LL) ? __expf(v1 - m) : 0.f;
        float s = e0 + e1;
        #pragma unroll
        for (int off = 16; off; off >>= 1)
            s += __shfl_xor_sync(0xffffffffu, s, off);
        float inv = 1.f / s;
        if (lane < LL) sw[lane] = e0 * inv;
        if (lane + 32 < LL) sw[lane + 32] = e1 * inv;
    }
    __syncthreads();

    // pass 2: attn[h] = sum_l w[l] * A[h][l]
    for (int h = tid; h < HH; h += 1024) {
        const float* row = sA + h * LL;
        float acc = 0.f;
        #pragma unroll
        for (int l = 0; l < LL; ++l) acc += sw[l] * row[l];
        g_a16[n * HH + h] = __float2half(acc);
    }
}

// ---------------- per-step GEMM: [x_t | h | attn](256x3072) @ W^T(3072x4096), split-K=2 ----------------
// fp16: dynamic side single, weights split hi/lo: C = A*Wh + A*Wl  (fp32 accumulate)
// 3-stage cp.async pipeline, ldmatrix fragment loads
#define SMS 5120   // 128*40 halfs per stage per matrix
#define NSTAGE 3

__device__ __forceinline__ void gemm_load_chunk(int t, int kc, int buf, int bm, int bn, int tid,
                                                hf* sAd, hf* sBh, hf* sBl, uint64_t pol) {
    const hf* pA; int kb;
    if (kc < 1024)      { pA = g_X16 + t * (NB * DD); kb = 0; }
    else if (kc < 2048) { pA = g_h16; kb = 1024; }
    else                { pA = g_a16; kb = 2048; }
    const int kA = kc - kb;
    // 3 matrices x 512 chunks of 16B, 256 threads -> 6 each
    #pragma unroll
    for (int j = 0; j < 6; ++j) {
        int v = tid + 256 * j;        // 0..1535
        int mat = v >> 9;             // 0=A 1=Bh 2=Bl
        int rem = v & 511;
        int row = rem >> 2, cq = rem & 3;
        int soff = buf * SMS + row * 40 + cq * 8;
        if (mat == 0) {
            cp16(sAd + soff, pA + (bm * 128 + row) * 1024 + kA + cq * 8);
        } else {
            size_t gB = (size_t)(bn * 128 + row) * K3 + kc + cq * 8;
            if (mat == 1) cp16_ll(sBh + soff, g_Wh16 + gB, pol);
            else          cp16_ll(sBl + soff, g_Wl16 + gB, pol);
        }
    }
    asm volatile("cp.async.commit_group;\n" ::);
}

__global__ void __launch_bounds__(256, 1) k_gemm(int t) {
    const int bm = blockIdx.x;   // 0..1
    const int bn = blockIdx.y;   // 0..31
    const int z  = blockIdx.z;   // 0..1 split-K
    extern __shared__ hf sm[];
    hf* sAd = sm;
    hf* sBh = sm + NSTAGE * SMS;
    hf* sBl = sm + 2 * NSTAGE * SMS;
    const int tid  = threadIdx.x;
    const int lane = tid & 31, w = tid >> 5;
    const int wm = w & 1, wn = w >> 1;          // 2x4 warp grid, warp tile 64x32
    const int lr = lane >> 2, lc = lane & 3;
    const uint64_t pol = mkpol_evict_last();

    // smem byte bases for ldmatrix
    const unsigned bAd = (unsigned)__cvta_generic_to_shared(sAd);
    const unsigned bBh = (unsigned)__cvta_generic_to_shared(sBh);
    const unsigned bBl = (unsigned)__cvta_generic_to_shared(sBl);
    // per-lane ldmatrix row offsets (bytes); row stride = 40 halfs = 80 B
    const unsigned aoff = (unsigned)((wm * 64 + (lane & 7) + ((lane >> 3) & 1) * 8) * 80
                                     + ((lane >> 4) & 1) * 16);
    const unsigned boff = (unsigned)((wn * 32 + (lane & 7)) * 80 + ((lane >> 3) & 1) * 16);

    float d[4][4][4];
    #pragma unroll
    for (int a = 0; a < 4; ++a)
        #pragma unroll
        for (int b2 = 0; b2 < 4; ++b2)
            #pragma unroll
            for (int c = 0; c < 4; ++c) d[a][b2][c] = 0.f;

    const int kc0 = z * 1536;
    gemm_load_chunk(t, kc0, 0, bm, bn, tid, sAd, sBh, sBl, pol);
    gemm_load_chunk(t, kc0 + 32, 1, bm, bn, tid, sAd, sBh, sBl, pol);

    int cb = 0;   // compute buffer
    int lb = 2;   // next load buffer
    for (int it = 0; it < 48; ++it) {
        asm volatile("cp.async.wait_group 1;\n" ::);
        __syncthreads();
        if (it + 2 < 48) {
            gemm_load_chunk(t, kc0 + (it + 2) * 32, lb, bm, bn, tid, sAd, sBh, sBl, pol);
            if (++lb == NSTAGE) lb = 0;
        }
        const unsigned cbo = (unsigned)(cb * SMS * 2);
        if (++cb == NSTAGE) cb = 0;
        #pragma unroll
        for (int kt = 0; kt < 32; kt += 16) {
            unsigned ad[4][4], bh[4][2], bl[4][2];
            #pragma unroll
            for (int mt = 0; mt < 4; ++mt) {
                unsigned o = cbo + (unsigned)(mt * 1280 + kt * 2) + aoff;
                ldsm_x4(ad[mt], bAd + o);
            }
            #pragma unroll
            for (int nt = 0; nt < 4; ++nt) {
                unsigned o = cbo + (unsigned)(nt * 640 + kt * 2) + boff;
                ldsm_x2(bh[nt], bBh + o);
                ldsm_x2(bl[nt], bBl + o);
            }
            #pragma unroll
            for (int mt = 0; mt < 4; ++mt)
                #pragma unroll
                for (int nt = 0; nt < 4; ++nt) {
                    mma16816(d[mt][nt], ad[mt], bh[nt]);
                    mma16816(d[mt][nt], ad[mt], bl[nt]);
                }
        }
        __syncthreads();
    }

    float* P = z ? g_P1 : g_P0;
    #pragma unroll
    for (int mt = 0; mt < 4; ++mt) {
        int r = bm * 128 + wm * 64 + mt * 16 + lr;
        #pragma unroll
        for (int nt = 0; nt < 4; ++nt) {
            int cN = bn * 128 + wn * 32 + nt * 8 + 2 * lc;
            float2 v0 = make_float2(d[mt][nt][0], d[mt][nt][1]);
            float2 v1 = make_float2(d[mt][nt][2], d[mt][nt][3]);
            *(float2*)&P[r * N4 + cN]       = v0;
            *(float2*)&P[(r + 8) * N4 + cN] = v1;
        }
    }
}

// ---------------- per-step gates + state update + output + h fp16 ----------------
__global__ void __launch_bounds__(256) k_gates(const float* __restrict__ bvec,
                                               float* __restrict__ out, int t) {
    int idx = blockIdx.x * 256 + threadIdx.x;    // over NB*HH
    int n = idx >> 10, j = idx & 1023;
    int base = n * N4 + j;
    float a0 = g_P0[base]          + g_P1[base]          + bvec[j];
    float a1 = g_P0[base + 1024]   + g_P1[base + 1024]   + bvec[j + 1024];
    float a2 = g_P0[base + 2048]   + g_P1[base + 2048]   + bvec[j + 2048];
    float a3 = g_P0[base + 3072]   + g_P1[base + 3072]   + bvec[j + 3072];
    float ig = 1.f / (1.f + expf(-a0));
    float fg = 1.f / (1.f + expf(-a1));
    float og = 1.f / (1.f + expf(-a2));
    float gg = tanhf(a3);
    float c = fg * g_c[idx] + ig * gg;
    g_c[idx] = c;
    float hn = og * tanhf(c);
    g_h[idx] = hn;
    out[(n * TT + t) * HH + j] = hn;
    g_h16[idx] = __float2half(hn);
}

// ---------------- launch ----------------
extern "C" void kernel_launch(void* const* d_in, const int* in_sizes, int n_in,
                              void* d_out, int out_size) {
    (void)in_sizes; (void)n_in; (void)out_size;
    const float* x     = (const float*)d_in[0];
    const float* A     = (const float*)d_in[1];
    const float* Wx    = (const float*)d_in[2];
    const float* Wh    = (const float*)d_in[3];
    const float* Wattn = (const float*)d_in[4];
    const float* bvec  = (const float*)d_in[5];
    float* out = (float*)d_out;

    const int gemmSmem = 3 * NSTAGE * SMS * (int)sizeof(hf);   // 92160
    const int attSmem  = HH * LL * (int)sizeof(float);         // 200704
    cudaFuncSetAttribute(k_gemm, cudaFuncAttributeMaxDynamicSharedMemorySize, gemmSmem);
    cudaFuncSetAttribute(k_att,  cudaFuncAttributeMaxDynamicSharedMemorySize, attSmem);

    k_prepX<<<(TT * NB * DD) / 256, 256>>>(x);
    k_prepW<<<dim3(K3 / 32, N4 / 32), dim3(32, 8)>>>(Wx, Wh, Wattn);
    k_init<<<(NB * HH) / 256, 256>>>(A);

    for (int t = 0; t < TT; ++t) {
        k_att<<<NB, 1024, attSmem>>>(A);
        k_gemm<<<dim3(2, 32, 2), 256, gemmSmem>>>(t);
        k_gates<<<(NB * HH) / 256, 256>>>(bvec, out, t);
    }
}

// round 9
// speedup vs baseline: 1.6662x; 1.0567x over previous
#include <cuda_runtime.h>
#include <cuda_fp16.h>
#include <cstdint>

#define NB 256
#define TT 128
#define DD 1024
#define HH 1024
#define LL 49
#define K3 3072
#define N4 4096

typedef __half hf;

// ---------------- scratch (static device globals; no runtime allocation) ----------------
__device__ __align__(256) hf    g_X16[TT * NB * DD];   // x fp16, layout [t][n][k]
__device__ __align__(256) hf    g_A16[NB * HH * LL];   // A fp16 (attention only)
__device__ __align__(256) hf    g_Wh16[N4 * K3];       // W concat transposed [n][k], fp16 hi
__device__ __align__(256) hf    g_Wl16[N4 * K3];       // fp16 lo (W - hi)
__device__ __align__(256) float g_h[NB * HH];
__device__ __align__(256) float g_c[NB * HH];
__device__ __align__(256) hf    g_h16[NB * HH];
__device__ __align__(256) hf    g_a16[NB * HH];        // attn fp16
__device__ __align__(256) float g_P0[NB * N4];         // split-K partial 0
__device__ __align__(256) float g_P1[NB * N4];         // split-K partial 1

__device__ __forceinline__ void cp16(const void* smem_dst, const void* gsrc) {
    unsigned s = (unsigned)__cvta_generic_to_shared((void*)smem_dst);
    asm volatile("cp.async.cg.shared.global [%0], [%1], 16;\n" :: "r"(s), "l"(gsrc));
}
__device__ __forceinline__ void cp16_ll(const void* smem_dst, const void* gsrc, uint64_t pol) {
    unsigned s = (unsigned)__cvta_generic_to_shared((void*)smem_dst);
    asm volatile("cp.async.cg.shared.global.L2::cache_hint [%0], [%1], 16, %2;\n"
                 :: "r"(s), "l"(gsrc), "l"(pol));
}
__device__ __forceinline__ uint64_t mkpol_evict_last() {
    uint64_t pol;
    asm("createpolicy.fractional.L2::evict_last.b64 %0, 1.0;" : "=l"(pol));
    return pol;
}

__device__ __forceinline__ void mma16816(float* d, const unsigned* a, const unsigned* b) {
    asm volatile(
        "mma.sync.aligned.m16n8k16.row.col.f32.f16.f16.f32 "
        "{%0,%1,%2,%3}, {%4,%5,%6,%7}, {%8,%9}, {%0,%1,%2,%3};\n"
        : "+f"(d[0]), "+f"(d[1]), "+f"(d[2]), "+f"(d[3])
        : "r"(a[0]), "r"(a[1]), "r"(a[2]), "r"(a[3]), "r"(b[0]), "r"(b[1]));
}

__device__ __forceinline__ void ldsm_x4(unsigned* r, unsigned addr) {
    asm volatile("ldmatrix.sync.aligned.m8n8.x4.shared.b16 {%0,%1,%2,%3}, [%4];"
                 : "=r"(r[0]), "=r"(r[1]), "=r"(r[2]), "=r"(r[3]) : "r"(addr));
}
__device__ __forceinline__ void ldsm_x2(unsigned* r, unsigned addr) {
    asm volatile("ldmatrix.sync.aligned.m8n8.x2.shared.b16 {%0,%1}, [%2];"
                 : "=r"(r[0]), "=r"(r[1]) : "r"(addr));
}

// ---------------- prep: x -> fp16 [t][n][k] ----------------
__global__ void __launch_bounds__(256) k_prepX(const float* __restrict__ x) {
    int idx = blockIdx.x * 256 + threadIdx.x;     // over T*N*D, x is (N,T,D)
    int k = idx & 1023;
    int r = idx >> 10;                            // n*TT + t
    int t = r & 127;
    int n = r >> 7;
    g_X16[(t * NB + n) * DD + k] = __float2half(x[idx]);
}

// ---------------- prep: A -> fp16 (flat; mirrors k_prepX structure) ----------------
// grid: NB*HH*LL/256 = 50176 blocks exactly (NB*HH*LL = 12845056 divisible by 256)
__global__ void __launch_bounds__(256) k_prepA(const float* __restrict__ A) {
    int idx = blockIdx.x * 256 + threadIdx.x;
    g_A16[idx] = __float2half(A[idx]);
}

// ---------------- prep: transpose + fp16 hi/lo split of weights ----------------
__global__ void k_prepW(const float* __restrict__ Wx, const float* __restrict__ Wh,
                        const float* __restrict__ Wattn) {
    __shared__ float tile[32][33];
    int k0 = blockIdx.x * 32, n0 = blockIdx.y * 32;
    int tx = threadIdx.x, ty = threadIdx.y;       // block (32,8)
    const float* src; int kb;
    if (k0 < 1024)      { src = Wx;    kb = 0; }
    else if (k0 < 2048) { src = Wh;    kb = 1024; }
    else                { src = Wattn; kb = 2048; }
    #pragma unroll
    for (int i = 0; i < 4; ++i) {
        int r = ty + i * 8;
        tile[r][tx] = src[(k0 - kb + r) * N4 + n0 + tx];
    }
    __syncthreads();
    #pragma unroll
    for (int i = 0; i < 4; ++i) {
        int r = ty + i * 8;
        int n = n0 + r, k = k0 + tx;
        float v = tile[tx][r];
        hf hi = __float2half(v);
        hf lo = __float2half(v - __half2float(hi));
        g_Wh16[n * K3 + k] = hi;
        g_Wl16[n * K3 + k] = lo;
    }
}

// ---------------- prep: h0 = c0 = mean over spatial dims of A (fp32 A, exact) ----------------
__global__ void __launch_bounds__(256) k_init(const float* __restrict__ A) {
    int idx = blockIdx.x * 256 + threadIdx.x;     // over NB*HH
    const float* Ap = A + (size_t)idx * LL;
    float s = 0.f;
    #pragma unroll
    for (int l = 0; l < LL; ++l) s += Ap[l];
    s *= (1.f / 49.f);
    g_h[idx] = s;
    g_c[idx] = s;
    g_h16[idx] = __float2half(s);
}

// ---------------- per-step attention: fp16 A slice SMEM-resident, read once ----------------
// grid NB, block 1024, dynamic smem = HH*LL*2 = 100352 B
#define ATT_CHUNKS ((HH * LL * 2) / 16)   // 6272 16B chunks
__global__ void __launch_bounds__(1024) k_att() {
    const int n = blockIdx.x;
    const int tid = threadIdx.x;
    const int lane = tid & 31, wid = tid >> 5;
    extern __shared__ hf sA16[];                  // [HH*LL] flat fp16
    __shared__ float sh[HH];
    __shared__ float sw[64];

    {
        const uint64_t pol = mkpol_evict_last();
        const uint4* Ap = (const uint4*)(g_A16 + (size_t)n * (HH * LL));
        uint4* dst = (uint4*)sA16;
        for (int i = tid; i < ATT_CHUNKS; i += 1024)
            cp16_ll(dst + i, Ap + i, pol);
        asm volatile("cp.async.commit_group;\n" ::);
        if (tid < HH) sh[tid] = g_h[n * HH + tid];
        asm volatile("cp.async.wait_group 0;\n" ::);
    }
    __syncthreads();

    // pass 1: scores[l] = sum_h A[h][l] * h[h]
    for (int l = wid; l < LL; l += 32) {
        float acc = 0.f;
        #pragma unroll 8
        for (int h = lane; h < HH; h += 32)
            acc += __half2float(sA16[h * LL + l]) * sh[h];
        #pragma unroll
        for (int off = 16; off; off >>= 1)
            acc += __shfl_xor_sync(0xffffffffu, acc, off);
        if (lane == 0) sw[l] = acc * 0.03125f;    // 1/sqrt(H)
    }
    __syncthreads();

    // softmax over 49 scores (warp 0, butterfly)
    if (wid == 0) {
        float v0 = (lane < LL) ? sw[lane] : -1e30f;
        float v1 = (lane + 32 < LL) ? sw[lane + 32] : -1e30f;
        float m = fmaxf(v0, v1);
        #pragma unroll
        for (int off = 16; off; off >>= 1)
            m = fmaxf(m, __shfl_xor_sync(0xffffffffu, m, off));
        float e0 = (lane < LL) ? __expf(v0 - m) : 0.f;
        float e1 = (lane + 32 < LL) ? __expf(v1 - m) : 0.f;
        float s = e0 + e1;
        #pragma unroll
        for (int off = 16; off; off >>= 1)
            s += __shfl_xor_sync(0xffffffffu, s, off);
        float inv = 1.f / s;
        if (lane < LL) sw[lane] = e0 * inv;
        if (lane + 32 < LL) sw[lane + 32] = e1 * inv;
    }
    __syncthreads();

    // pass 2: attn[h] = sum_l w[l] * A[h][l]
    for (int h = tid; h < HH; h += 1024) {
        const hf* row = sA16 + h * LL;
        float acc = 0.f;
        #pragma unroll
        for (int l = 0; l < LL; ++l) acc += sw[l] * __half2float(row[l]);
        g_a16[n * HH + h] = __float2half(acc);
    }
}

// ---------------- per-step GEMM: [x_t | h | attn](256x3072) @ W^T(3072x4096), split-K=2 ----------------
// fp16: dynamic side single, weights split hi/lo: C = A*Wh + A*Wl  (fp32 accumulate)
// 3-stage cp.async pipeline, ldmatrix fragment loads
#define SMS 5120   // 128*40 halfs per stage per matrix
#define NSTAGE 3

__device__ __forceinline__ void gemm_load_chunk(int t, int kc, int buf, int bm, int bn, int tid,
                                                hf* sAd, hf* sBh, hf* sBl, uint64_t pol) {
    const hf* pA; int kb;
    if (kc < 1024)      { pA = g_X16 + t * (NB * DD); kb = 0; }
    else if (kc < 2048) { pA = g_h16; kb = 1024; }
    else                { pA = g_a16; kb = 2048; }
    const int kA = kc - kb;
    // 3 matrices x 512 chunks of 16B, 256 threads -> 6 each
    #pragma unroll
    for (int j = 0; j < 6; ++j) {
        int v = tid + 256 * j;        // 0..1535
        int mat = v >> 9;             // 0=A 1=Bh 2=Bl
        int rem = v & 511;
        int row = rem >> 2, cq = rem & 3;
        int soff = buf * SMS + row * 40 + cq * 8;
        if (mat == 0) {
            cp16(sAd + soff, pA + (bm * 128 + row) * 1024 + kA + cq * 8);
        } else {
            size_t gB = (size_t)(bn * 128 + row) * K3 + kc + cq * 8;
            if (mat == 1) cp16_ll(sBh + soff, g_Wh16 + gB, pol);
            else          cp16_ll(sBl + soff, g_Wl16 + gB, pol);
        }
    }
    asm volatile("cp.async.commit_group;\n" ::);
}

__global__ void __launch_bounds__(256, 1) k_gemm(int t) {
    const int bm = blockIdx.x;   // 0..1
    const int bn = blockIdx.y;   // 0..31
    const int z  = blockIdx.z;   // 0..1 split-K
    extern __shared__ hf sm[];
    hf* sAd = sm;
    hf* sBh = sm + NSTAGE * SMS;
    hf* sBl = sm + 2 * NSTAGE * SMS;
    const int tid  = threadIdx.x;
    const int lane = tid & 31, w = tid >> 5;
    const int wm = w & 1, wn = w >> 1;          // 2x4 warp grid, warp tile 64x32
    const int lr = lane >> 2, lc = lane & 3;
    const uint64_t pol = mkpol_evict_last();

    // smem byte bases for ldmatrix
    const unsigned bAd = (unsigned)__cvta_generic_to_shared(sAd);
    const unsigned bBh = (unsigned)__cvta_generic_to_shared(sBh);
    const unsigned bBl = (unsigned)__cvta_generic_to_shared(sBl);
    // per-lane ldmatrix row offsets (bytes); row stride = 40 halfs = 80 B
    const unsigned aoff = (unsigned)((wm * 64 + (lane & 7) + ((lane >> 3) & 1) * 8) * 80
                                     + ((lane >> 4) & 1) * 16);
    const unsigned boff = (unsigned)((wn * 32 + (lane & 7)) * 80 + ((lane >> 3) & 1) * 16);

    float d[4][4][4];
    #pragma unroll
    for (int a = 0; a < 4; ++a)
        #pragma unroll
        for (int b2 = 0; b2 < 4; ++b2)
            #pragma unroll
            for (int c = 0; c < 4; ++c) d[a][b2][c] = 0.f;

    const int kc0 = z * 1536;
    gemm_load_chunk(t, kc0, 0, bm, bn, tid, sAd, sBh, sBl, pol);
    gemm_load_chunk(t, kc0 + 32, 1, bm, bn, tid, sAd, sBh, sBl, pol);

    int cb = 0;   // compute buffer
    int lb = 2;   // next load buffer
    for (int it = 0; it < 48; ++it) {
        asm volatile("cp.async.wait_group 1;\n" ::);
        __syncthreads();
        if (it + 2 < 48) {
            gemm_load_chunk(t, kc0 + (it + 2) * 32, lb, bm, bn, tid, sAd, sBh, sBl, pol);
            if (++lb == NSTAGE) lb = 0;
        }
        const unsigned cbo = (unsigned)(cb * SMS * 2);
        if (++cb == NSTAGE) cb = 0;
        #pragma unroll
        for (int kt = 0; kt < 32; kt += 16) {
            unsigned ad[4][4], bh[4][2], bl[4][2];
            #pragma unroll
            for (int mt = 0; mt < 4; ++mt) {
                unsigned o = cbo + (unsigned)(mt * 1280 + kt * 2) + aoff;
                ldsm_x4(ad[mt], bAd + o);
            }
            #pragma unroll
            for (int nt = 0; nt < 4; ++nt) {
                unsigned o = cbo + (unsigned)(nt * 640 + kt * 2) + boff;
                ldsm_x2(bh[nt], bBh + o);
                ldsm_x2(bl[nt], bBl + o);
            }
            #pragma unroll
            for (int mt = 0; mt < 4; ++mt)
                #pragma unroll
                for (int nt = 0; nt < 4; ++nt) {
                    mma16816(d[mt][nt], ad[mt], bh[nt]);
                    mma16816(d[mt][nt], ad[mt], bl[nt]);
                }
        }
        __syncthreads();
    }

    float* P = z ? g_P1 : g_P0;
    #pragma unroll
    for (int mt = 0; mt < 4; ++mt) {
        int r = bm * 128 + wm * 64 + mt * 16 + lr;
        #pragma unroll
        for (int nt = 0; nt < 4; ++nt) {
            int cN = bn * 128 + wn * 32 + nt * 8 + 2 * lc;
            float2 v0 = make_float2(d[mt][nt][0], d[mt][nt][1]);
            float2 v1 = make_float2(d[mt][nt][2], d[mt][nt][3]);
            *(float2*)&P[r * N4 + cN]       = v0;
            *(float2*)&P[(r + 8) * N4 + cN] = v1;
        }
    }
}

// ---------------- per-step gates + state update + output + h fp16 ----------------
__global__ void __launch_bounds__(256) k_gates(const float* __restrict__ bvec,
                                               float* __restrict__ out, int t) {
    int idx = blockIdx.x * 256 + threadIdx.x;    // over NB*HH
    int n = idx >> 10, j = idx & 1023;
    int base = n * N4 + j;
    float a0 = g_P0[base]          + g_P1[base]          + bvec[j];
    float a1 = g_P0[base + 1024]   + g_P1[base + 1024]   + bvec[j + 1024];
    float a2 = g_P0[base + 2048]   + g_P1[base + 2048]   + bvec[j + 2048];
    float a3 = g_P0[base + 3072]   + g_P1[base + 3072]   + bvec[j + 3072];
    float ig = 1.f / (1.f + expf(-a0));
    float fg = 1.f / (1.f + expf(-a1));
    float og = 1.f / (1.f + expf(-a2));
    float gg = tanhf(a3);
    float c = fg * g_c[idx] + ig * gg;
    g_c[idx] = c;
    float hn = og * tanhf(c);
    g_h[idx] = hn;
    out[(n * TT + t) * HH + j] = hn;
    g_h16[idx] = __float2half(hn);
}

// ---------------- launch ----------------
extern "C" void kernel_launch(void* const* d_in, const int* in_sizes, int n_in,
                              void* d_out, int out_size) {
    (void)in_sizes; (void)n_in; (void)out_size;
    const float* x     = (const float*)d_in[0];
    const float* A     = (const float*)d_in[1];
    const float* Wx    = (const float*)d_in[2];
    const float* Wh    = (const float*)d_in[3];
    const float* Wattn = (const float*)d_in[4];
    const float* bvec  = (const float*)d_in[5];
    float* out = (float*)d_out;

    const int gemmSmem = 3 * NSTAGE * SMS * (int)sizeof(hf);   // 92160
    const int attSmem  = HH * LL * (int)sizeof(hf);            // 100352
    cudaFuncSetAttribute(k_gemm, cudaFuncAttributeMaxDynamicSharedMemorySize, gemmSmem);
    cudaFuncSetAttribute(k_att,  cudaFuncAttributeMaxDynamicSharedMemorySize, attSmem);

    k_prepX<<<(TT * NB * DD) / 256, 256>>>(x);
    k_prepA<<<(NB * HH * LL) / 256, 256>>>(A);
    k_prepW<<<dim3(K3 / 32, N4 / 32), dim3(32, 8)>>>(Wx, Wh, Wattn);
    k_init<<<(NB * HH) / 256, 256>>>(A);

    for (int t = 0; t < TT; ++t) {
        k_att<<<NB, 1024, attSmem>>>();
        k_gemm<<<dim3(2, 32, 2), 256, gemmSmem>>>(t);
        k_gates<<<(NB * HH) / 256, 256>>>(bvec, out, t);
    }
}

// round 11
// speedup vs baseline: 1.7197x; 1.0321x over previous
#include <cuda_runtime.h>
#include <cuda_fp16.h>
#include <cstdint>

#define NB 256
#define TT 128
#define DD 1024
#define HH 1024
#define LL 49
#define K3 3072
#define N4 4096

typedef __half hf;

// ---------------- scratch (static device globals; no runtime allocation) ----------------
__device__ __align__(256) hf    g_X16[TT * NB * DD];   // x fp16, layout [t][n][k] == row-major (T*NB) x DD
__device__ __align__(256) hf    g_A16[NB * HH * LL];   // A fp16 (attention only)
__device__ __align__(256) hf    g_Wh16[N4 * K3];       // W concat transposed [n][k], fp16 hi
__device__ __align__(256) hf    g_Wl16[N4 * K3];       // fp16 lo (W - hi)
__device__ __align__(256) float g_h[NB * HH];
__device__ __align__(256) float g_c[NB * HH];
__device__ __align__(256) hf    g_h16[NB * HH];
__device__ __align__(256) hf    g_a16[NB * HH];        // attn fp16
__device__ __align__(256) float g_P0[NB * N4];         // split-K partial (h|attn) 0
__device__ __align__(256) float g_P1[NB * N4];         // split-K partial (h|attn) 1
__device__ __align__(256) hf    g_Z16[(size_t)TT * NB * N4];  // x@Wx for all t, fp16 (268 MB)

__device__ __forceinline__ void cp16(const void* smem_dst, const void* gsrc) {
    unsigned s = (unsigned)__cvta_generic_to_shared((void*)smem_dst);
    asm volatile("cp.async.cg.shared.global [%0], [%1], 16;\n" :: "r"(s), "l"(gsrc));
}
__device__ __forceinline__ void cp16_ll(const void* smem_dst, const void* gsrc, uint64_t pol) {
    unsigned s = (unsigned)__cvta_generic_to_shared((void*)smem_dst);
    asm volatile("cp.async.cg.shared.global.L2::cache_hint [%0], [%1], 16, %2;\n"
                 :: "r"(s), "l"(gsrc), "l"(pol));
}
__device__ __forceinline__ uint64_t mkpol_evict_last() {
    uint64_t pol;
    asm("createpolicy.fractional.L2::evict_last.b64 %0, 1.0;" : "=l"(pol));
    return pol;
}

__device__ __forceinline__ void mma16816(float* d, const unsigned* a, const unsigned* b) {
    asm volatile(
        "mma.sync.aligned.m16n8k16.row.col.f32.f16.f16.f32 "
        "{%0,%1,%2,%3}, {%4,%5,%6,%7}, {%8,%9}, {%0,%1,%2,%3};\n"
        : "+f"(d[0]), "+f"(d[1]), "+f"(d[2]), "+f"(d[3])
        : "r"(a[0]), "r"(a[1]), "r"(a[2]), "r"(a[3]), "r"(b[0]), "r"(b[1]));
}

__device__ __forceinline__ void ldsm_x4(unsigned* r, unsigned addr) {
    asm volatile("ldmatrix.sync.aligned.m8n8.x4.shared.b16 {%0,%1,%2,%3}, [%4];"
                 : "=r"(r[0]), "=r"(r[1]), "=r"(r[2]), "=r"(r[3]) : "r"(addr));
}
__device__ __forceinline__ void ldsm_x2(unsigned* r, unsigned addr) {
    asm volatile("ldmatrix.sync.aligned.m8n8.x2.shared.b16 {%0,%1}, [%2];"
                 : "=r"(r[0]), "=r"(r[1]) : "r"(addr));
}

// ---------------- prep: x -> fp16 [t][n][k] ----------------
__global__ void __launch_bounds__(256) k_prepX(const float* __restrict__ x) {
    int idx = blockIdx.x * 256 + threadIdx.x;     // over T*N*D, x is (N,T,D)
    int k = idx & 1023;
    int r = idx >> 10;                            // n*TT + t
    int t = r & 127;
    int n = r >> 7;
    g_X16[(t * NB + n) * DD + k] = __float2half(x[idx]);
}

// ---------------- prep: A -> fp16 (flat) ----------------
__global__ void __launch_bounds__(256) k_prepA(const float* __restrict__ A) {
    int idx = blockIdx.x * 256 + threadIdx.x;
    g_A16[idx] = __float2half(A[idx]);
}

// ---------------- prep: transpose + fp16 hi/lo split of weights ----------------
__global__ void k_prepW(const float* __restrict__ Wx, const float* __restrict__ Wh,
                        const float* __restrict__ Wattn) {
    __shared__ float tile[32][33];
    int k0 = blockIdx.x * 32, n0 = blockIdx.y * 32;
    int tx = threadIdx.x, ty = threadIdx.y;       // block (32,8)
    const float* src; int kb;
    if (k0 < 1024)      { src = Wx;    kb = 0; }
    else if (k0 < 2048) { src = Wh;    kb = 1024; }
    else                { src = Wattn; kb = 2048; }
    #pragma unroll
    for (int i = 0; i < 4; ++i) {
        int r = ty + i * 8;
        tile[r][tx] = src[(k0 - kb + r) * N4 + n0 + tx];
    }
    __syncthreads();
    #pragma unroll
    for (int i = 0; i < 4; ++i) {
        int r = ty + i * 8;
        int n = n0 + r, k = k0 + tx;
        float v = tile[tx][r];
        hf hi = __float2half(v);
        hf lo = __float2half(v - __half2float(hi));
        g_Wh16[n * K3 + k] = hi;
        g_Wl16[n * K3 + k] = lo;
    }
}

// ---------------- prep: h0 = c0 = mean over spatial dims of A (fp32 A, exact) ----------------
__global__ void __launch_bounds__(256) k_init(const float* __restrict__ A) {
    int idx = blockIdx.x * 256 + threadIdx.x;     // over NB*HH
    const float* Ap = A + (size_t)idx * LL;
    float s = 0.f;
    #pragma unroll
    for (int l = 0; l < LL; ++l) s += Ap[l];
    s *= (1.f / 49.f);
    g_h[idx] = s;
    g_c[idx] = s;
    g_h16[idx] = __float2half(s);
}

// ---------------- per-step attention: fp16 A slice SMEM-resident, read once ----------------
#define ATT_CHUNKS ((HH * LL * 2) / 16)   // 6272 16B chunks
__global__ void __launch_bounds__(1024) k_att() {
    const int n = blockIdx.x;
    const int tid = threadIdx.x;
    const int lane = tid & 31, wid = tid >> 5;
    extern __shared__ hf sA16[];                  // [HH*LL] flat fp16
    __shared__ float sh[HH];
    __shared__ float sw[64];

    {
        const uint64_t pol = mkpol_evict_last();
        const uint4* Ap = (const uint4*)(g_A16 + (size_t)n * (HH * LL));
        uint4* dst = (uint4*)sA16;
        for (int i = tid; i < ATT_CHUNKS; i += 1024)
            cp16_ll(dst + i, Ap + i, pol);
        asm volatile("cp.async.commit_group;\n" ::);
        if (tid < HH) sh[tid] = g_h[n * HH + tid];
        asm volatile("cp.async.wait_group 0;\n" ::);
    }
    __syncthreads();

    // pass 1: scores[l] = sum_h A[h][l] * h[h]
    for (int l = wid; l < LL; l += 32) {
        float acc = 0.f;
        #pragma unroll 8
        for (int h = lane; h < HH; h += 32)
            acc += __half2float(sA16[h * LL + l]) * sh[h];
        #pragma unroll
        for (int off = 16; off; off >>= 1)
            acc += __shfl_xor_sync(0xffffffffu, acc, off);
        if (lane == 0) sw[l] = acc * 0.03125f;    // 1/sqrt(H)
    }
    __syncthreads();

    // softmax over 49 scores (warp 0, butterfly)
    if (wid == 0) {
        float v0 = (lane < LL) ? sw[lane] : -1e30f;
        float v1 = (lane + 32 < LL) ? sw[lane + 32] : -1e30f;
        float m = fmaxf(v0, v1);
        #pragma unroll
        for (int off = 16; off; off >>= 1)
            m = fmaxf(m, __shfl_xor_sync(0xffffffffu, m, off));
        float e0 = (lane < LL) ? __expf(v0 - m) : 0.f;
        float e1 = (lane + 32 < LL) ? __expf(v1 - m) : 0.f;
        float s = e0 + e1;
        #pragma unroll
        for (int off = 16; off; off >>= 1)
            s += __shfl_xor_sync(0xffffffffu, s, off);
        float inv = 1.f / s;
        if (lane < LL) sw[lane] = e0 * inv;
        if (lane + 32 < LL) sw[lane + 32] = e1 * inv;
    }
    __syncthreads();

    // pass 2: attn[h] = sum_l w[l] * A[h][l]
    for (int h = tid; h < HH; h += 1024) {
        const hf* row = sA16 + h * LL;
        float acc = 0.f;
        #pragma unroll
        for (int l = 0; l < LL; ++l) acc += sw[l] * __half2float(row[l]);
        g_a16[n * HH + h] = __float2half(acc);
    }
}

// ---------------- GEMM: 128x128 tile, K=1024 per (mode,z) ----------------
// mode 0 (prep, once): Z = X @ Wx for ALL t.  grid (256, 32, 1). A = g_X16 (32768 x 1024),
//                      kc in [0,1024), out = g_Z16 (fp16).
// mode 1 (per step):   P_z = [h|attn] @ W.    grid (2, 32, 2). kc0 = 1024 + z*1024,
//                      out = g_P0 / g_P1 (fp32).
#define SMS 5120   // 128*40 halfs per stage per matrix
#define NSTAGE 3

__device__ __forceinline__ void gemm_load_chunk(int kc, int buf, int bm, int bn, int tid,
                                                int mode, hf* sAd, hf* sBh, hf* sBl,
                                                uint64_t pol) {
    const hf* pA; int kA;
    if (mode == 0)      { pA = g_X16; kA = kc; }
    else if (kc < 2048) { pA = g_h16; kA = kc - 1024; }
    else                { pA = g_a16; kA = kc - 2048; }
    #pragma unroll
    for (int j = 0; j < 6; ++j) {
        int v = tid + 256 * j;        // 0..1535
        int mat = v >> 9;             // 0=A 1=Bh 2=Bl
        int rem = v & 511;
        int row = rem >> 2, cq = rem & 3;
        int soff = buf * SMS + row * 40 + cq * 8;
        if (mat == 0) {
            cp16(sAd + soff, pA + (bm * 128 + row) * 1024 + kA + cq * 8);
        } else {
            size_t gB = (size_t)(bn * 128 + row) * K3 + kc + cq * 8;
            if (mat == 1) cp16_ll(sBh + soff, g_Wh16 + gB, pol);
            else          cp16_ll(sBl + soff, g_Wl16 + gB, pol);
        }
    }
    asm volatile("cp.async.commit_group;\n" ::);
}

__global__ void __launch_bounds__(256, 1) k_gemm(int mode) {
    const int bm = blockIdx.x;   // mode0: 0..255 (rows of X);  mode1: 0..1
    const int bn = blockIdx.y;   // 0..31
    const int z  = blockIdx.z;   // mode0: 0;  mode1: 0..1 split-K
    extern __shared__ hf sm[];
    hf* sAd = sm;
    hf* sBh = sm + NSTAGE * SMS;
    hf* sBl = sm + 2 * NSTAGE * SMS;
    const int tid  = threadIdx.x;
    const int lane = tid & 31, w = tid >> 5;
    const int wm = w & 1, wn = w >> 1;          // 2x4 warp grid, warp tile 64x32
    const int lr = lane >> 2, lc = lane & 3;
    const uint64_t pol = mkpol_evict_last();

    const unsigned bAd = (unsigned)__cvta_generic_to_shared(sAd);
    const unsigned bBh = (unsigned)__cvta_generic_to_shared(sBh);
    const unsigned bBl = (unsigned)__cvta_generic_to_shared(sBl);
    const unsigned aoff = (unsigned)((wm * 64 + (lane & 7) + ((lane >> 3) & 1) * 8) * 80
                                     + ((lane >> 4) & 1) * 16);
    const unsigned boff = (unsigned)((wn * 32 + (lane & 7)) * 80 + ((lane >> 3) & 1) * 16);

    float d[4][4][4];
    #pragma unroll
    for (int a = 0; a < 4; ++a)
        #pragma unroll
        for (int b2 = 0; b2 < 4; ++b2)
            #pragma unroll
            for (int c = 0; c < 4; ++c) d[a][b2][c] = 0.f;

    const int kc0 = mode ? (1024 + z * 1024) : 0;
    gemm_load_chunk(kc0,      0, bm, bn, tid, mode, sAd, sBh, sBl, pol);
    gemm_load_chunk(kc0 + 32, 1, bm, bn, tid, mode, sAd, sBh, sBl, pol);

    int cb = 0;
    int lb = 2;
    for (int it = 0; it < 32; ++it) {
        asm volatile("cp.async.wait_group 1;\n" ::);
        __syncthreads();
        if (it + 2 < 32) {
            gemm_load_chunk(kc0 + (it + 2) * 32, lb, bm, bn, tid, mode, sAd, sBh, sBl, pol);
            if (++lb == NSTAGE) lb = 0;
        }
        const unsigned cbo = (unsigned)(cb * SMS * 2);
        if (++cb == NSTAGE) cb = 0;
        #pragma unroll
        for (int kt = 0; kt < 32; kt += 16) {
            unsigned ad[4][4], bh[4][2], bl[4][2];
            #pragma unroll
            for (int mt = 0; mt < 4; ++mt) {
                unsigned o = cbo + (unsigned)(mt * 1280 + kt * 2) + aoff;
                ldsm_x4(ad[mt], bAd + o);
            }
            #pragma unroll
            for (int nt = 0; nt < 4; ++nt) {
                unsigned o = cbo + (unsigned)(nt * 640 + kt * 2) + boff;
                ldsm_x2(bh[nt], bBh + o);
                ldsm_x2(bl[nt], bBl + o);
            }
            #pragma unroll
            for (int mt = 0; mt < 4; ++mt)
                #pragma unroll
                for (int nt = 0; nt < 4; ++nt) {
                    mma16816(d[mt][nt], ad[mt], bh[nt]);
                    mma16816(d[mt][nt], ad[mt], bl[nt]);
                }
        }
        __syncthreads();
    }

    if (mode == 0) {
        // fp16 output into g_Z16, global rows (covers all t)
        #pragma unroll
        for (int mt = 0; mt < 4; ++mt) {
            size_t r = (size_t)(bm * 128 + wm * 64 + mt * 16 + lr);
            #pragma unroll
            for (int nt = 0; nt < 4; ++nt) {
                int cN = bn * 128 + wn * 32 + nt * 8 + 2 * lc;
                __half2 v0 = __floats2half2_rn(d[mt][nt][0], d[mt][nt][1]);
                __half2 v1 = __floats2half2_rn(d[mt][nt][2], d[mt][nt][3]);
                *(__half2*)&g_Z16[r * N4 + cN]       = v0;
                *(__half2*)&g_Z16[(r + 8) * N4 + cN] = v1;
            }
        }
    } else {
        float* P = z ? g_P1 : g_P0;
        #pragma unroll
        for (int mt = 0; mt < 4; ++mt) {
            int r = bm * 128 + wm * 64 + mt * 16 + lr;
            #pragma unroll
            for (int nt = 0; nt < 4; ++nt) {
                int cN = bn * 128 + wn * 32 + nt * 8 + 2 * lc;
                float2 v0 = make_float2(d[mt][nt][0], d[mt][nt][1]);
                float2 v1 = make_float2(d[mt][nt][2], d[mt][nt][3]);
                *(float2*)&P[r * N4 + cN]       = v0;
                *(float2*)&P[(r + 8) * N4 + cN] = v1;
            }
        }
    }
}

// ---------------- per-step gates + state update + output + h fp16 ----------------
__global__ void __launch_bounds__(256) k_gates(const float* __restrict__ bvec,
                                               float* __restrict__ out, int t) {
    int idx = blockIdx.x * 256 + threadIdx.x;    // over NB*HH
    int n = idx >> 10, j = idx & 1023;
    int base = n * N4 + j;
    const hf* Zt = g_Z16 + (size_t)t * NB * N4;
    float a0 = g_P0[base]        + g_P1[base]        + __half2float(Zt[base])        + bvec[j];
    float a1 = g_P0[base + 1024] + g_P1[base + 1024] + __half2float(Zt[base + 1024]) + bvec[j + 1024];
    float a2 = g_P0[base + 2048] + g_P1[base + 2048] + __half2float(Zt[base + 2048]) + bvec[j + 2048];
    float a3 = g_P0[base + 3072] + g_P1[base + 3072] + __half2float(Zt[base + 3072]) + bvec[j + 3072];
    float ig = 1.f / (1.f + expf(-a0));
    float fg = 1.f / (1.f + expf(-a1));
    float og = 1.f / (1.f + expf(-a2));
    float gg = tanhf(a3);
    float c = fg * g_c[idx] + ig * gg;
    g_c[idx] = c;
    float hn = og * tanhf(c);
    g_h[idx] = hn;
    out[(n * TT + t) * HH + j] = hn;
    g_h16[idx] = __float2half(hn);
}

// ---------------- launch ----------------
extern "C" void kernel_launch(void* const* d_in, const int* in_sizes, int n_in,
                              void* d_out, int out_size) {
    (void)in_sizes; (void)n_in; (void)out_size;
    const float* x     = (const float*)d_in[0];
    const float* A     = (const float*)d_in[1];
    const float* Wx    = (const float*)d_in[2];
    const float* Wh    = (const float*)d_in[3];
    const float* Wattn = (const float*)d_in[4];
    const float* bvec  = (const float*)d_in[5];
    float* out = (float*)d_out;

    const int gemmSmem = 3 * NSTAGE * SMS * (int)sizeof(hf);   // 92160
    const int attSmem  = HH * LL * (int)sizeof(hf);            // 100352
    cudaFuncSetAttribute(k_gemm, cudaFuncAttributeMaxDynamicSharedMemorySize, gemmSmem);
    cudaFuncSetAttribute(k_att,  cudaFuncAttributeMaxDynamicSharedMemorySize, attSmem);

    // prep
    k_prepX<<<(TT * NB * DD) / 256, 256>>>(x);
    k_prepA<<<(NB * HH * LL) / 256, 256>>>(A);
    k_prepW<<<dim3(K3 / 32, N4 / 32), dim3(32, 8)>>>(Wx, Wh, Wattn);
    k_init<<<(NB * HH) / 256, 256>>>(A);

    // one big batched GEMM: Z[t] = x_t @ Wx for ALL t (off the recurrent critical path)
    k_gemm<<<dim3(TT * NB / 128, 32, 1), 256, gemmSmem>>>(0);

    for (int t = 0; t < TT; ++t) {
        k_att<<<NB, 1024, attSmem>>>();
        k_gemm<<<dim3(2, 32, 2), 256, gemmSmem>>>(1);           // [h|attn] @ W
        k_gates<<<(NB * HH) / 256, 256>>>(bvec, out, t);
    }
}

// round 12
// speedup vs baseline: 1.7479x; 1.0164x over previous
#include <cuda_runtime.h>
#include <cuda_fp16.h>
#include <cstdint>

#define NB 256
#define TT 128
#define DD 1024
#define HH 1024
#define LL 49
#define K3 3072
#define N4 4096

typedef __half hf;

// ---------------- scratch (static device globals; no runtime allocation) ----------------
__device__ __align__(256) hf    g_X16[TT * NB * DD];   // x fp16, [t][n][k] == row-major (T*NB) x DD
__device__ __align__(256) hf    g_A16[NB * HH * LL];   // A fp16 (attention only)
__device__ __align__(256) hf    g_Wh16[N4 * K3];       // W concat transposed [n][k], fp16 hi
__device__ __align__(256) hf    g_Wl16[N4 * K3];       // fp16 lo (W - hi)
__device__ __align__(256) float g_h[NB * HH];
__device__ __align__(256) float g_c[NB * HH];
__device__ __align__(256) hf    g_h16[NB * HH];
__device__ __align__(256) hf    g_a16[NB * HH];        // attn fp16
__device__ __align__(256) float g_P0[NB * N4];         // h-slice partial z=0
__device__ __align__(256) float g_P1[NB * N4];         // h-slice partial z=1
__device__ __align__(256) float g_P2[NB * N4];         // attn-slice partial z=0
__device__ __align__(256) float g_P3[NB * N4];         // attn-slice partial z=1
__device__ __align__(256) hf    g_Z16[(size_t)TT * NB * N4];  // x@Wx for all t, fp16

__device__ __forceinline__ void cp16(const void* smem_dst, const void* gsrc) {
    unsigned s = (unsigned)__cvta_generic_to_shared((void*)smem_dst);
    asm volatile("cp.async.cg.shared.global [%0], [%1], 16;\n" :: "r"(s), "l"(gsrc));
}
__device__ __forceinline__ void cp16_ll(const void* smem_dst, const void* gsrc, uint64_t pol) {
    unsigned s = (unsigned)__cvta_generic_to_shared((void*)smem_dst);
    asm volatile("cp.async.cg.shared.global.L2::cache_hint [%0], [%1], 16, %2;\n"
                 :: "r"(s), "l"(gsrc), "l"(pol));
}
__device__ __forceinline__ uint64_t mkpol_evict_last() {
    uint64_t pol;
    asm("createpolicy.fractional.L2::evict_last.b64 %0, 1.0;" : "=l"(pol));
    return pol;
}

__device__ __forceinline__ void mma16816(float* d, const unsigned* a, const unsigned* b) {
    asm volatile(
        "mma.sync.aligned.m16n8k16.row.col.f32.f16.f16.f32 "
        "{%0,%1,%2,%3}, {%4,%5,%6,%7}, {%8,%9}, {%0,%1,%2,%3};\n"
        : "+f"(d[0]), "+f"(d[1]), "+f"(d[2]), "+f"(d[3])
        : "r"(a[0]), "r"(a[1]), "r"(a[2]), "r"(a[3]), "r"(b[0]), "r"(b[1]));
}

__device__ __forceinline__ void ldsm_x4(unsigned* r, unsigned addr) {
    asm volatile("ldmatrix.sync.aligned.m8n8.x4.shared.b16 {%0,%1,%2,%3}, [%4];"
                 : "=r"(r[0]), "=r"(r[1]), "=r"(r[2]), "=r"(r[3]) : "r"(addr));
}
__device__ __forceinline__ void ldsm_x2(unsigned* r, unsigned addr) {
    asm volatile("ldmatrix.sync.aligned.m8n8.x2.shared.b16 {%0,%1}, [%2];"
                 : "=r"(r[0]), "=r"(r[1]) : "r"(addr));
}

// ---------------- prep kernels ----------------
__global__ void __launch_bounds__(256) k_prepX(const float* __restrict__ x) {
    int idx = blockIdx.x * 256 + threadIdx.x;     // over T*N*D, x is (N,T,D)
    int k = idx & 1023;
    int r = idx >> 10;                            // n*TT + t
    int t = r & 127;
    int n = r >> 7;
    g_X16[(t * NB + n) * DD + k] = __float2half(x[idx]);
}

__global__ void __launch_bounds__(256) k_prepA(const float* __restrict__ A) {
    int idx = blockIdx.x * 256 + threadIdx.x;
    g_A16[idx] = __float2half(A[idx]);
}

__global__ void k_prepW(const float* __restrict__ Wx, const float* __restrict__ Wh,
                        const float* __restrict__ Wattn) {
    __shared__ float tile[32][33];
    int k0 = blockIdx.x * 32, n0 = blockIdx.y * 32;
    int tx = threadIdx.x, ty = threadIdx.y;       // block (32,8)
    const float* src; int kb;
    if (k0 < 1024)      { src = Wx;    kb = 0; }
    else if (k0 < 2048) { src = Wh;    kb = 1024; }
    else                { src = Wattn; kb = 2048; }
    #pragma unroll
    for (int i = 0; i < 4; ++i) {
        int r = ty + i * 8;
        tile[r][tx] = src[(k0 - kb + r) * N4 + n0 + tx];
    }
    __syncthreads();
    #pragma unroll
    for (int i = 0; i < 4; ++i) {
        int r = ty + i * 8;
        int n = n0 + r, k = k0 + tx;
        float v = tile[tx][r];
        hf hi = __float2half(v);
        hf lo = __float2half(v - __half2float(hi));
        g_Wh16[n * K3 + k] = hi;
        g_Wl16[n * K3 + k] = lo;
    }
}

__global__ void __launch_bounds__(256) k_init(const float* __restrict__ A) {
    int idx = blockIdx.x * 256 + threadIdx.x;     // over NB*HH
    const float* Ap = A + (size_t)idx * LL;
    float s = 0.f;
    #pragma unroll
    for (int l = 0; l < LL; ++l) s += Ap[l];
    s *= (1.f / 49.f);
    g_h[idx] = s;
    g_c[idx] = s;
    g_h16[idx] = __float2half(s);
}

// ---------------- GEMM tile body: 128x128 tile, nchunks k-chunks of 32 ----------------
// kc semantics: [0,1024)=X (prep), [1024,2048)=h16, [2048,3072)=a16; B = W hi/lo at kc.
#define SMS 5120   // 128*40 halfs per stage per matrix
#define NSTAGE 3

__device__ __forceinline__ void gemm_load_chunk(int kc, int buf, int bm, int bn, int tid,
                                                hf* sAd, hf* sBh, hf* sBl, uint64_t pol) {
    const hf* pA; int kA;
    if (kc < 1024)      { pA = g_X16; kA = kc; }
    else if (kc < 2048) { pA = g_h16; kA = kc - 1024; }
    else                { pA = g_a16; kA = kc - 2048; }
    #pragma unroll
    for (int j = 0; j < 6; ++j) {
        int v = tid + 256 * j;        // 0..1535
        int mat = v >> 9;             // 0=A 1=Bh 2=Bl
        int rem = v & 511;
        int row = rem >> 2, cq = rem & 3;
        int soff = buf * SMS + row * 40 + cq * 8;
        if (mat == 0) {
            cp16(sAd + soff, pA + (bm * 128 + row) * 1024 + kA + cq * 8);
        } else {
            size_t gB = (size_t)(bn * 128 + row) * K3 + kc + cq * 8;
            if (mat == 1) cp16_ll(sBh + soff, g_Wh16 + gB, pol);
            else          cp16_ll(sBl + soff, g_Wl16 + gB, pol);
        }
    }
    asm volatile("cp.async.commit_group;\n" ::);
}

template <bool TOZ>
__device__ __forceinline__ void gemm_tile(int kc0, int nchunks, int bm, int bn,
                                          float* P, hf* sm) {
    hf* sAd = sm;
    hf* sBh = sm + NSTAGE * SMS;
    hf* sBl = sm + 2 * NSTAGE * SMS;
    const int tid  = threadIdx.x;
    const int lane = tid & 31, w = tid >> 5;
    const int wm = w & 1, wn = w >> 1;          // 2x4 warp grid, warp tile 64x32
    const int lr = lane >> 2, lc = lane & 3;
    const uint64_t pol = mkpol_evict_last();

    const unsigned bAd = (unsigned)__cvta_generic_to_shared(sAd);
    const unsigned bBh = (unsigned)__cvta_generic_to_shared(sBh);
    const unsigned bBl = (unsigned)__cvta_generic_to_shared(sBl);
    const unsigned aoff = (unsigned)((wm * 64 + (lane & 7) + ((lane >> 3) & 1) * 8) * 80
                                     + ((lane >> 4) & 1) * 16);
    const unsigned boff = (unsigned)((wn * 32 + (lane & 7)) * 80 + ((lane >> 3) & 1) * 16);

    float d[4][4][4];
    #pragma unroll
    for (int a = 0; a < 4; ++a)
        #pragma unroll
        for (int b2 = 0; b2 < 4; ++b2)
            #pragma unroll
            for (int c = 0; c < 4; ++c) d[a][b2][c] = 0.f;

    gemm_load_chunk(kc0,      0, bm, bn, tid, sAd, sBh, sBl, pol);
    gemm_load_chunk(kc0 + 32, 1, bm, bn, tid, sAd, sBh, sBl, pol);

    int cb = 0;
    int lb = 2;
    for (int it = 0; it < nchunks; ++it) {
        asm volatile("cp.async.wait_group 1;\n" ::);
        __syncthreads();
        if (it + 2 < nchunks) {
            gemm_load_chunk(kc0 + (it + 2) * 32, lb, bm, bn, tid, sAd, sBh, sBl, pol);
            if (++lb == NSTAGE) lb = 0;
        }
        const unsigned cbo = (unsigned)(cb * SMS * 2);
        if (++cb == NSTAGE) cb = 0;
        #pragma unroll
        for (int kt = 0; kt < 32; kt += 16) {
            unsigned ad[4][4], bh[4][2], bl[4][2];
            #pragma unroll
            for (int mt = 0; mt < 4; ++mt) {
                unsigned o = cbo + (unsigned)(mt * 1280 + kt * 2) + aoff;
                ldsm_x4(ad[mt], bAd + o);
            }
            #pragma unroll
            for (int nt = 0; nt < 4; ++nt) {
                unsigned o = cbo + (unsigned)(nt * 640 + kt * 2) + boff;
                ldsm_x2(bh[nt], bBh + o);
                ldsm_x2(bl[nt], bBl + o);
            }
            #pragma unroll
            for (int mt = 0; mt < 4; ++mt)
                #pragma unroll
                for (int nt = 0; nt < 4; ++nt) {
                    mma16816(d[mt][nt], ad[mt], bh[nt]);
                    mma16816(d[mt][nt], ad[mt], bl[nt]);
                }
        }
        __syncthreads();
    }

    if (TOZ) {
        #pragma unroll
        for (int mt = 0; mt < 4; ++mt) {
            size_t r = (size_t)(bm * 128 + wm * 64 + mt * 16 + lr);
            #pragma unroll
            for (int nt = 0; nt < 4; ++nt) {
                int cN = bn * 128 + wn * 32 + nt * 8 + 2 * lc;
                __half2 v0 = __floats2half2_rn(d[mt][nt][0], d[mt][nt][1]);
                __half2 v1 = __floats2half2_rn(d[mt][nt][2], d[mt][nt][3]);
                *(__half2*)&g_Z16[r * N4 + cN]       = v0;
                *(__half2*)&g_Z16[(r + 8) * N4 + cN] = v1;
            }
        }
    } else {
        #pragma unroll
        for (int mt = 0; mt < 4; ++mt) {
            int r = bm * 128 + wm * 64 + mt * 16 + lr;
            #pragma unroll
            for (int nt = 0; nt < 4; ++nt) {
                int cN = bn * 128 + wn * 32 + nt * 8 + 2 * lc;
                float2 v0 = make_float2(d[mt][nt][0], d[mt][nt][1]);
                float2 v1 = make_float2(d[mt][nt][2], d[mt][nt][3]);
                *(float2*)&P[r * N4 + cN]       = v0;
                *(float2*)&P[(r + 8) * N4 + cN] = v1;
            }
        }
    }
}

// ---------------- attention body (256 threads) ----------------
#define ATT_CHUNKS ((HH * LL * 2) / 16)   // 6272 16B chunks
__device__ __forceinline__ void att_body(int n, hf* sA16) {
    const int tid = threadIdx.x;
    const int lane = tid & 31, wid = tid >> 5;
    __shared__ float sh[HH];
    __shared__ float sw[64];

    {
        const uint64_t pol = mkpol_evict_last();
        const uint4* Ap = (const uint4*)(g_A16 + (size_t)n * (HH * LL));
        uint4* dst = (uint4*)sA16;
        for (int i = tid; i < ATT_CHUNKS; i += 256)
            cp16_ll(dst + i, Ap + i, pol);
        asm volatile("cp.async.commit_group;\n" ::);
        for (int i = tid; i < HH; i += 256) sh[i] = g_h[n * HH + i];
        asm volatile("cp.async.wait_group 0;\n" ::);
    }
    __syncthreads();

    // pass 1: scores[l] = sum_h A[h][l] * h[h]  (8 warps, l strided by 8)
    for (int l = wid; l < LL; l += 8) {
        float acc = 0.f;
        #pragma unroll 8
        for (int h = lane; h < HH; h += 32)
            acc += __half2float(sA16[h * LL + l]) * sh[h];
        #pragma unroll
        for (int off = 16; off; off >>= 1)
            acc += __shfl_xor_sync(0xffffffffu, acc, off);
        if (lane == 0) sw[l] = acc * 0.03125f;    // 1/sqrt(H)
    }
    __syncthreads();

    // softmax over 49 scores (warp 0)
    if (wid == 0) {
        float v0 = (lane < LL) ? sw[lane] : -1e30f;
        float v1 = (lane + 32 < LL) ? sw[lane + 32] : -1e30f;
        float m = fmaxf(v0, v1);
        #pragma unroll
        for (int off = 16; off; off >>= 1)
            m = fmaxf(m, __shfl_xor_sync(0xffffffffu, m, off));
        float e0 = (lane < LL) ? __expf(v0 - m) : 0.f;
        float e1 = (lane + 32 < LL) ? __expf(v1 - m) : 0.f;
        float s = e0 + e1;
        #pragma unroll
        for (int off = 16; off; off >>= 1)
            s += __shfl_xor_sync(0xffffffffu, s, off);
        float inv = 1.f / s;
        if (lane < LL) sw[lane] = e0 * inv;
        if (lane + 32 < LL) sw[lane + 32] = e1 * inv;
    }
    __syncthreads();

    // pass 2: attn[h] = sum_l w[l] * A[h][l]
    for (int h = tid; h < HH; h += 256) {
        const hf* row = sA16 + h * LL;
        float acc = 0.f;
        #pragma unroll
        for (int l = 0; l < LL; ++l) acc += sw[l] * __half2float(row[l]);
        g_a16[n * HH + h] = __float2half(acc);
    }
}

// ---------------- fused per-step kernel: h-GEMM (blocks 0..127) + attention (128..383) ----------------
__global__ void __launch_bounds__(256) k_fused() {
    extern __shared__ hf smu[];
    if (blockIdx.x < 128) {
        int bid = blockIdx.x;
        int bm = bid & 1, bn = (bid >> 1) & 31, z = bid >> 6;   // split-K=2 over h slice
        gemm_tile<false>(1024 + z * 512, 16, bm, bn, z ? g_P1 : g_P0, smu);
    } else {
        att_body(blockIdx.x - 128, smu);
    }
}

// ---------------- attn-slice GEMM (after k_fused) ----------------
__global__ void __launch_bounds__(256) k_gemm2() {
    extern __shared__ hf smu[];
    int bm = blockIdx.x, bn = blockIdx.y, z = blockIdx.z;
    gemm_tile<false>(2048 + z * 512, 16, bm, bn, z ? g_P3 : g_P2, smu);
}

// ---------------- prep GEMM: Z = X @ Wx for all t ----------------
__global__ void __launch_bounds__(256) k_gemmZ() {
    extern __shared__ hf smu[];
    gemm_tile<true>(0, 32, blockIdx.x, blockIdx.y, nullptr, smu);
}

// ---------------- per-step gates + state update + output + h fp16 ----------------
__global__ void __launch_bounds__(256) k_gates(const float* __restrict__ bvec,
                                               float* __restrict__ out, int t) {
    int idx = blockIdx.x * 256 + threadIdx.x;    // over NB*HH
    int n = idx >> 10, j = idx & 1023;
    int base = n * N4 + j;
    const hf* Zt = g_Z16 + (size_t)t * NB * N4;
    float a0 = g_P0[base]        + g_P1[base]        + g_P2[base]        + g_P3[base]
             + __half2float(Zt[base])        + bvec[j];
    float a1 = g_P0[base + 1024] + g_P1[base + 1024] + g_P2[base + 1024] + g_P3[base + 1024]
             + __half2float(Zt[base + 1024]) + bvec[j + 1024];
    float a2 = g_P0[base + 2048] + g_P1[base + 2048] + g_P2[base + 2048] + g_P3[base + 2048]
             + __half2float(Zt[base + 2048]) + bvec[j + 2048];
    float a3 = g_P0[base + 3072] + g_P1[base + 3072] + g_P2[base + 3072] + g_P3[base + 3072]
             + __half2float(Zt[base + 3072]) + bvec[j + 3072];
    float ig = 1.f / (1.f + expf(-a0));
    float fg = 1.f / (1.f + expf(-a1));
    float og = 1.f / (1.f + expf(-a2));
    float gg = tanhf(a3);
    float c = fg * g_c[idx] + ig * gg;
    g_c[idx] = c;
    float hn = og * tanhf(c);
    g_h[idx] = hn;
    out[(n * TT + t) * HH + j] = hn;
    g_h16[idx] = __float2half(hn);
}

// ---------------- launch ----------------
extern "C" void kernel_launch(void* const* d_in, const int* in_sizes, int n_in,
                              void* d_out, int out_size) {
    (void)in_sizes; (void)n_in; (void)out_size;
    const float* x     = (const float*)d_in[0];
    const float* A     = (const float*)d_in[1];
    const float* Wx    = (const float*)d_in[2];
    const float* Wh    = (const float*)d_in[3];
    const float* Wattn = (const float*)d_in[4];
    const float* bvec  = (const float*)d_in[5];
    float* out = (float*)d_out;

    const int gemmSmem = 3 * NSTAGE * SMS * (int)sizeof(hf);   // 92160
    const int attSmem  = HH * LL * (int)sizeof(hf);            // 100352 (>= gemmSmem)
    cudaFuncSetAttribute(k_gemmZ, cudaFuncAttributeMaxDynamicSharedMemorySize, gemmSmem);
    cudaFuncSetAttribute(k_gemm2, cudaFuncAttributeMaxDynamicSharedMemorySize, gemmSmem);
    cudaFuncSetAttribute(k_fused, cudaFuncAttributeMaxDynamicSharedMemorySize, attSmem);

    // prep
    k_prepX<<<(TT * NB * DD) / 256, 256>>>(x);
    k_prepA<<<(NB * HH * LL) / 256, 256>>>(A);
    k_prepW<<<dim3(K3 / 32, N4 / 32), dim3(32, 8)>>>(Wx, Wh, Wattn);
    k_init<<<(NB * HH) / 256, 256>>>(A);

    // one big batched GEMM: Z[t] = x_t @ Wx for ALL t
    k_gemmZ<<<dim3(TT * NB / 128, 32), 256, gemmSmem>>>();

    for (int t = 0; t < TT; ++t) {
        k_fused<<<384, 256, attSmem>>>();                       // h-GEMM || attention
        k_gemm2<<<dim3(2, 32, 2), 256, gemmSmem>>>();           // attn-slice GEMM
        k_gates<<<(NB * HH) / 256, 256>>>(bvec, out, t);
    }
}

// round 14
// speedup vs baseline: 1.7566x; 1.0050x over previous
#include <cuda_runtime.h>
#include <cuda_fp16.h>
#include <cstdint>

#define NB 256
#define TT 128
#define DD 1024
#define HH 1024
#define LL 49
#define K3 3072
#define N4 4096

typedef __half hf;

// ---------------- scratch (static device globals; no runtime allocation) ----------------
__device__ __align__(256) hf    g_X16[TT * NB * DD];   // x fp16, [t][n][k]
__device__ __align__(256) hf    g_A16[NB * HH * LL];   // A fp16 (attention only)
__device__ __align__(256) hf    g_Wh16[N4 * K3];       // W concat transposed [n][k], fp16 hi
__device__ __align__(256) hf    g_Wl16[N4 * K3];       // fp16 lo (W - hi)
__device__ __align__(256) float g_h[NB * HH];
__device__ __align__(256) float g_c[NB * HH];
__device__ __align__(256) hf    g_h16[NB * HH];
__device__ __align__(256) hf    g_a16[NB * HH];        // attn fp16
__device__ __align__(256) hf    g_P0[NB * N4];         // h-slice partial z=0 (fp16)
__device__ __align__(256) hf    g_P1[NB * N4];         // h-slice partial z=1
__device__ __align__(256) hf    g_P2[NB * N4];         // attn-slice partial z=0
__device__ __align__(256) hf    g_P3[NB * N4];         // attn-slice partial z=1
__device__ __align__(256) hf    g_Z16[(size_t)TT * NB * N4];  // x@Wx for all t, fp16

__device__ __forceinline__ void cp16(const void* smem_dst, const void* gsrc) {
    unsigned s = (unsigned)__cvta_generic_to_shared((void*)smem_dst);
    asm volatile("cp.async.cg.shared.global [%0], [%1], 16;\n" :: "r"(s), "l"(gsrc));
}
__device__ __forceinline__ void cp16_ll(const void* smem_dst, const void* gsrc, uint64_t pol) {
    unsigned s = (unsigned)__cvta_generic_to_shared((void*)smem_dst);
    asm volatile("cp.async.cg.shared.global.L2::cache_hint [%0], [%1], 16, %2;\n"
                 :: "r"(s), "l"(gsrc), "l"(pol));
}
__device__ __forceinline__ uint64_t mkpol_evict_last() {
    uint64_t pol;
    asm("createpolicy.fractional.L2::evict_last.b64 %0, 1.0;" : "=l"(pol));
    return pol;
}

__device__ __forceinline__ void mma16816(float* d, const unsigned* a, const unsigned* b) {
    asm volatile(
        "mma.sync.aligned.m16n8k16.row.col.f32.f16.f16.f32 "
        "{%0,%1,%2,%3}, {%4,%5,%6,%7}, {%8,%9}, {%0,%1,%2,%3};\n"
        : "+f"(d[0]), "+f"(d[1]), "+f"(d[2]), "+f"(d[3])
        : "r"(a[0]), "r"(a[1]), "r"(a[2]), "r"(a[3]), "r"(b[0]), "r"(b[1]));
}

__device__ __forceinline__ void ldsm_x4(unsigned* r, unsigned addr) {
    asm volatile("ldmatrix.sync.aligned.m8n8.x4.shared.b16 {%0,%1,%2,%3}, [%4];"
                 : "=r"(r[0]), "=r"(r[1]), "=r"(r[2]), "=r"(r[3]) : "r"(addr));
}
__device__ __forceinline__ void ldsm_x2(unsigned* r, unsigned addr) {
    asm volatile("ldmatrix.sync.aligned.m8n8.x2.shared.b16 {%0,%1}, [%2];"
                 : "=r"(r[0]), "=r"(r[1]) : "r"(addr));
}

// ---------------- prep kernels ----------------
__global__ void __launch_bounds__(256) k_prepX(const float* __restrict__ x) {
    int idx = blockIdx.x * 256 + threadIdx.x;     // over T*N*D, x is (N,T,D)
    int k = idx & 1023;
    int r = idx >> 10;                            // n*TT + t
    int t = r & 127;
    int n = r >> 7;
    g_X16[(t * NB + n) * DD + k] = __float2half(x[idx]);
}

__global__ void __launch_bounds__(256) k_prepA(const float* __restrict__ A) {
    int idx = blockIdx.x * 256 + threadIdx.x;
    g_A16[idx] = __float2half(A[idx]);
}

__global__ void k_prepW(const float* __restrict__ Wx, const float* __restrict__ Wh,
                        const float* __restrict__ Wattn) {
    __shared__ float tile[32][33];
    int k0 = blockIdx.x * 32, n0 = blockIdx.y * 32;
    int tx = threadIdx.x, ty = threadIdx.y;       // block (32,8)
    const float* src; int kb;
    if (k0 < 1024)      { src = Wx;    kb = 0; }
    else if (k0 < 2048) { src = Wh;    kb = 1024; }
    else                { src = Wattn; kb = 2048; }
    #pragma unroll
    for (int i = 0; i < 4; ++i) {
        int r = ty + i * 8;
        tile[r][tx] = src[(k0 - kb + r) * N4 + n0 + tx];
    }
    __syncthreads();
    #pragma unroll
    for (int i = 0; i < 4; ++i) {
        int r = ty + i * 8;
        int n = n0 + r, k = k0 + tx;
        float v = tile[tx][r];
        hf hi = __float2half(v);
        hf lo = __float2half(v - __half2float(hi));
        g_Wh16[n * K3 + k] = hi;
        g_Wl16[n * K3 + k] = lo;
    }
}

__global__ void __launch_bounds__(256) k_init(const float* __restrict__ A) {
    int idx = blockIdx.x * 256 + threadIdx.x;     // over NB*HH
    const float* Ap = A + (size_t)idx * LL;
    float s = 0.f;
    #pragma unroll
    for (int l = 0; l < LL; ++l) s += Ap[l];
    s *= (1.f / 49.f);
    g_h[idx] = s;
    g_c[idx] = s;
    g_h16[idx] = __float2half(s);
}

// ---------------- GEMM tile body: 128x128 tile, nchunks k-chunks of 32 ----------------
// kc semantics: [0,1024)=X (prep), [1024,2048)=h16, [2048,3072)=a16; B = W hi/lo at kc.
// W streams with default policy; only A16 (attention) carries evict_last.
#define SMS 5120   // 128*40 halfs per stage per matrix
#define NSTAGE 3

__device__ __forceinline__ void gemm_load_chunk(int kc, int buf, int bm, int bn, int tid,
                                                hf* sAd, hf* sBh, hf* sBl) {
    const hf* pA; int kA;
    if (kc < 1024)      { pA = g_X16; kA = kc; }
    else if (kc < 2048) { pA = g_h16; kA = kc - 1024; }
    else                { pA = g_a16; kA = kc - 2048; }
    #pragma unroll
    for (int j = 0; j < 6; ++j) {
        int v = tid + 256 * j;        // 0..1535
        int mat = v >> 9;             // 0=A 1=Bh 2=Bl
        int rem = v & 511;
        int row = rem >> 2, cq = rem & 3;
        int soff = buf * SMS + row * 40 + cq * 8;
        if (mat == 0) {
            cp16(sAd + soff, pA + (bm * 128 + row) * 1024 + kA + cq * 8);
        } else {
            size_t gB = (size_t)(bn * 128 + row) * K3 + kc + cq * 8;
            if (mat == 1) cp16(sBh + soff, g_Wh16 + gB);
            else          cp16(sBl + soff, g_Wl16 + gB);
        }
    }
    asm volatile("cp.async.commit_group;\n" ::);
}

template <bool TOZ>
__device__ __forceinline__ void gemm_tile(int kc0, int nchunks, int bm, int bn,
                                          hf* P, hf* sm) {
    hf* sAd = sm;
    hf* sBh = sm + NSTAGE * SMS;
    hf* sBl = sm + 2 * NSTAGE * SMS;
    const int tid  = threadIdx.x;
    const int lane = tid & 31, w = tid >> 5;
    const int wm = w & 1, wn = w >> 1;          // 2x4 warp grid, warp tile 64x32
    const int lr = lane >> 2, lc = lane & 3;

    const unsigned bAd = (unsigned)__cvta_generic_to_shared(sAd);
    const unsigned bBh = (unsigned)__cvta_generic_to_shared(sBh);
    const unsigned bBl = (unsigned)__cvta_generic_to_shared(sBl);
    const unsigned aoff = (unsigned)((wm * 64 + (lane & 7) + ((lane >> 3) & 1) * 8) * 80
                                     + ((lane >> 4) & 1) * 16);
    const unsigned boff = (unsigned)((wn * 32 + (lane & 7)) * 80 + ((lane >> 3) & 1) * 16);

    float d[4][4][4];
    #pragma unroll
    for (int a = 0; a < 4; ++a)
        #pragma unroll
        for (int b2 = 0; b2 < 4; ++b2)
            #pragma unroll
            for (int c = 0; c < 4; ++c) d[a][b2][c] = 0.f;

    gemm_load_chunk(kc0,      0, bm, bn, tid, sAd, sBh, sBl);
    gemm_load_chunk(kc0 + 32, 1, bm, bn, tid, sAd, sBh, sBl);

    int cb = 0;
    int lb = 2;
    for (int it = 0; it < nchunks; ++it) {
        asm volatile("cp.async.wait_group 1;\n" ::);
        __syncthreads();
        if (it + 2 < nchunks) {
            gemm_load_chunk(kc0 + (it + 2) * 32, lb, bm, bn, tid, sAd, sBh, sBl);
            if (++lb == NSTAGE) lb = 0;
        }
        const unsigned cbo = (unsigned)(cb * SMS * 2);
        if (++cb == NSTAGE) cb = 0;
        #pragma unroll
        for (int kt = 0; kt < 32; kt += 16) {
            unsigned ad[4][4], bh[4][2], bl[4][2];
            #pragma unroll
            for (int mt = 0; mt < 4; ++mt) {
                unsigned o = cbo + (unsigned)(mt * 1280 + kt * 2) + aoff;
                ldsm_x4(ad[mt], bAd + o);
            }
            #pragma unroll
            for (int nt = 0; nt < 4; ++nt) {
                unsigned o = cbo + (unsigned)(nt * 640 + kt * 2) + boff;
                ldsm_x2(bh[nt], bBh + o);
                ldsm_x2(bl[nt], bBl + o);
            }
            #pragma unroll
            for (int mt = 0; mt < 4; ++mt)
                #pragma unroll
                for (int nt = 0; nt < 4; ++nt) {
                    mma16816(d[mt][nt], ad[mt], bh[nt]);
                    mma16816(d[mt][nt], ad[mt], bl[nt]);
                }
        }
        __syncthreads();
    }

    if (TOZ) {
        #pragma unroll
        for (int mt = 0; mt < 4; ++mt) {
            size_t r = (size_t)(bm * 128 + wm * 64 + mt * 16 + lr);
            #pragma unroll
            for (int nt = 0; nt < 4; ++nt) {
                int cN = bn * 128 + wn * 32 + nt * 8 + 2 * lc;
                __half2 v0 = __floats2half2_rn(d[mt][nt][0], d[mt][nt][1]);
                __half2 v1 = __floats2half2_rn(d[mt][nt][2], d[mt][nt][3]);
                *(__half2*)&g_Z16[r * N4 + cN]       = v0;
                *(__half2*)&g_Z16[(r + 8) * N4 + cN] = v1;
            }
        }
    } else {
        #pragma unroll
        for (int mt = 0; mt < 4; ++mt) {
            int r = bm * 128 + wm * 64 + mt * 16 + lr;
            #pragma unroll
            for (int nt = 0; nt < 4; ++nt) {
                int cN = bn * 128 + wn * 32 + nt * 8 + 2 * lc;
                __half2 v0 = __floats2half2_rn(d[mt][nt][0], d[mt][nt][1]);
                __half2 v1 = __floats2half2_rn(d[mt][nt][2], d[mt][nt][3]);
                *(__half2*)&P[r * N4 + cN]       = v0;
                *(__half2*)&P[(r + 8) * N4 + cN] = v1;
            }
        }
    }
}

// ---------------- attention body (256 threads) ----------------
#define ATT_CHUNKS ((HH * LL * 2) / 16)   // 6272 16B chunks
__device__ __forceinline__ void att_body(int n, hf* sA16) {
    const int tid = threadIdx.x;
    const int lane = tid & 31, wid = tid >> 5;
    __shared__ float sh[HH];
    __shared__ float sw[64];

    {
        const uint64_t pol = mkpol_evict_last();
        const uint4* Ap = (const uint4*)(g_A16 + (size_t)n * (HH * LL));
        uint4* dst = (uint4*)sA16;
        for (int i = tid; i < ATT_CHUNKS; i += 256)
            cp16_ll(dst + i, Ap + i, pol);
        asm volatile("cp.async.commit_group;\n" ::);
        for (int i = tid; i < HH; i += 256) sh[i] = g_h[n * HH + i];
        asm volatile("cp.async.wait_group 0;\n" ::);
    }
    __syncthreads();

    // pass 1: scores[l] = sum_h A[h][l] * h[h]
    for (int l = wid; l < LL; l += 8) {
        float acc = 0.f;
        #pragma unroll 8
        for (int h = lane; h < HH; h += 32)
            acc += __half2float(sA16[h * LL + l]) * sh[h];
        #pragma unroll
        for (int off = 16; off; off >>= 1)
            acc += __shfl_xor_sync(0xffffffffu, acc, off);
        if (lane == 0) sw[l] = acc * 0.03125f;    // 1/sqrt(H)
    }
    __syncthreads();

    // softmax over 49 scores (warp 0)
    if (wid == 0) {
        float v0 = (lane < LL) ? sw[lane] : -1e30f;
        float v1 = (lane + 32 < LL) ? sw[lane + 32] : -1e30f;
        float m = fmaxf(v0, v1);
        #pragma unroll
        for (int off = 16; off; off >>= 1)
            m = fmaxf(m, __shfl_xor_sync(0xffffffffu, m, off));
        float e0 = (lane < LL) ? __expf(v0 - m) : 0.f;
        float e1 = (lane + 32 < LL) ? __expf(v1 - m) : 0.f;
        float s = e0 + e1;
        #pragma unroll
        for (int off = 16; off; off >>= 1)
            s += __shfl_xor_sync(0xffffffffu, s, off);
        float inv = 1.f / s;
        if (lane < LL) sw[lane] = e0 * inv;
        if (lane + 32 < LL) sw[lane + 32] = e1 * inv;
    }
    __syncthreads();

    // pass 2: attn[h] = sum_l w[l] * A[h][l]
    for (int h = tid; h < HH; h += 256) {
        const hf* row = sA16 + h * LL;
        float acc = 0.f;
        #pragma unroll
        for (int l = 0; l < LL; ++l) acc += sw[l] * __half2float(row[l]);
        g_a16[n * HH + h] = __float2half(acc);
    }
}

// ---------------- fused per-step kernel: h-GEMM (blocks 0..127) + attention (128..383) ----------------
__global__ void __launch_bounds__(256) k_fused() {
    extern __shared__ hf smu[];
    if (blockIdx.x < 128) {
        int bid = blockIdx.x;
        int bm = bid & 1, bn = (bid >> 1) & 31, z = bid >> 6;   // split-K=2 over h slice
        gemm_tile<false>(1024 + z * 512, 16, bm, bn, z ? g_P1 : g_P0, smu);
    } else {
        att_body(blockIdx.x - 128, smu);
    }
}

// ---------------- attn-slice GEMM (after k_fused) ----------------
__global__ void __launch_bounds__(256) k_gemm2() {
    extern __shared__ hf smu[];
    int bm = blockIdx.x, bn = blockIdx.y, z = blockIdx.z;
    gemm_tile<false>(2048 + z * 512, 16, bm, bn, z ? g_P3 : g_P2, smu);
}

// ---------------- prep GEMM: Z = X @ Wx for all t ----------------
__global__ void __launch_bounds__(256) k_gemmZ() {
    extern __shared__ hf smu[];
    gemm_tile<true>(0, 32, blockIdx.x, blockIdx.y, nullptr, smu);
}

// ---------------- per-step gates + state update + output + h fp16 ----------------
__global__ void __launch_bounds__(256) k_gates(const float* __restrict__ bvec,
                                               float* __restrict__ out, int t) {
    int idx = blockIdx.x * 256 + threadIdx.x;    // over NB*HH
    int n = idx >> 10, j = idx & 1023;
    int base = n * N4 + j;
    const hf* Zt = g_Z16 + (size_t)t * NB * N4;
    float a0 = __half2float(g_P0[base])        + __half2float(g_P1[base])
             + __half2float(g_P2[base])        + __half2float(g_P3[base])
             + __half2float(Zt[base])          + bvec[j];
    float a1 = __half2float(g_P0[base + 1024]) + __half2float(g_P1[base + 1024])
             + __half2float(g_P2[base + 1024]) + __half2float(g_P3[base + 1024])
             + __half2float(Zt[base + 1024])   + bvec[j + 1024];
    float a2 = __half2float(g_P0[base + 2048]) + __half2float(g_P1[base + 2048])
             + __half2float(g_P2[base + 2048]) + __half2float(g_P3[base + 2048])
             + __half2float(Zt[base + 2048])   + bvec[j + 2048];
    float a3 = __half2float(g_P0[base + 3072]) + __half2float(g_P1[base + 3072])
             + __half2float(g_P2[base + 3072]) + __half2float(g_P3[base + 3072])
             + __half2float(Zt[base + 3072])   + bvec[j + 3072];
    float ig = 1.f / (1.f + expf(-a0));
    float fg = 1.f / (1.f + expf(-a1));
    float og = 1.f / (1.f + expf(-a2));
    float gg = tanhf(a3);
    float c = fg * g_c[idx] + ig * gg;
    g_c[idx] = c;
    float hn = og * tanhf(c);
    g_h[idx] = hn;
    out[(n * TT + t) * HH + j] = hn;
    g_h16[idx] = __float2half(hn);
}

// ---------------- launch ----------------
extern "C" void kernel_launch(void* const* d_in, const int* in_sizes, int n_in,
                              void* d_out, int out_size) {
    (void)in_sizes; (void)n_in; (void)out_size;
    const float* x     = (const float*)d_in[0];
    const float* A     = (const float*)d_in[1];
    const float* Wx    = (const float*)d_in[2];
    const float* Wh    = (const float*)d_in[3];
    const float* Wattn = (const float*)d_in[4];
    const float* bvec  = (const float*)d_in[5];
    float* out = (float*)d_out;

    const int gemmSmem = 3 * NSTAGE * SMS * (int)sizeof(hf);   // 92160
    const int attSmem  = HH * LL * (int)sizeof(hf);            // 100352 (>= gemmSmem)
    cudaFuncSetAttribute(k_gemmZ, cudaFuncAttributeMaxDynamicSharedMemorySize, gemmSmem);
    cudaFuncSetAttribute(k_gemm2, cudaFuncAttributeMaxDynamicSharedMemorySize, gemmSmem);
    cudaFuncSetAttribute(k_fused, cudaFuncAttributeMaxDynamicSharedMemorySize, attSmem);

    // prep
    k_prepX<<<(TT * NB * DD) / 256, 256>>>(x);
    k_prepA<<<(NB * HH * LL) / 256, 256>>>(A);
    k_prepW<<<dim3(K3 / 32, N4 / 32), dim3(32, 8)>>>(Wx, Wh, Wattn);
    k_init<<<(NB * HH) / 256, 256>>>(A);

    // one big batched GEMM: Z[t] = x_t @ Wx for ALL t
    k_gemmZ<<<dim3(TT * NB / 128, 32), 256, gemmSmem>>>();

    for (int t = 0; t < TT; ++t) {
        k_fused<<<384, 256, attSmem>>>();                       // h-GEMM || attention
        k_gemm2<<<dim3(2, 32, 2), 256, gemmSmem>>>();           // attn-slice GEMM
        k_gates<<<(NB * HH) / 256, 256>>>(bvec, out, t);
    }
}

// round 15
// speedup vs baseline: 2.3234x; 1.3227x over previous
#include <cuda_runtime.h>
#include <cuda_fp16.h>
#include <cstdint>

#define NB 256
#define TT 128
#define DD 1024
#define HH 1024
#define LL 49
#define K3 3072
#define N4 4096

typedef __half hf;

// ---------------- scratch (static device globals; no runtime allocation) ----------------
__device__ __align__(256) hf    g_X16[TT * NB * DD];   // x fp16, [t][n][k]
__device__ __align__(256) hf    g_A16[NB * HH * LL];   // A fp16 (attention only)
__device__ __align__(256) hf    g_Wh16[N4 * K3];       // W concat transposed [n][k], fp16 hi
__device__ __align__(256) hf    g_Wl16[N4 * K3];       // fp16 lo (W - hi); used only by Z prep
__device__ __align__(256) float g_h[NB * HH];
__device__ __align__(256) float g_c[NB * HH];
__device__ __align__(256) hf    g_h16[NB * HH];
__device__ __align__(256) hf    g_a16[NB * HH];        // attn fp16
__device__ __align__(256) hf    g_P0[NB * N4];         // h-slice partial z=0 (fp16)
__device__ __align__(256) hf    g_P1[NB * N4];         // h-slice partial z=1
__device__ __align__(256) hf    g_P2[NB * N4];         // attn-slice partial z=0
__device__ __align__(256) hf    g_P3[NB * N4];         // attn-slice partial z=1
__device__ __align__(256) hf    g_Z16[(size_t)TT * NB * N4];  // x@Wx for all t, fp16

__device__ __forceinline__ void cp16(const void* smem_dst, const void* gsrc) {
    unsigned s = (unsigned)__cvta_generic_to_shared((void*)smem_dst);
    asm volatile("cp.async.cg.shared.global [%0], [%1], 16;\n" :: "r"(s), "l"(gsrc));
}
__device__ __forceinline__ void cp16_ll(const void* smem_dst, const void* gsrc, uint64_t pol) {
    unsigned s = (unsigned)__cvta_generic_to_shared((void*)smem_dst);
    asm volatile("cp.async.cg.shared.global.L2::cache_hint [%0], [%1], 16, %2;\n"
                 :: "r"(s), "l"(gsrc), "l"(pol));
}
__device__ __forceinline__ uint64_t mkpol_evict_last() {
    uint64_t pol;
    asm("createpolicy.fractional.L2::evict_last.b64 %0, 1.0;" : "=l"(pol));
    return pol;
}

__device__ __forceinline__ void mma16816(float* d, const unsigned* a, const unsigned* b) {
    asm volatile(
        "mma.sync.aligned.m16n8k16.row.col.f32.f16.f16.f32 "
        "{%0,%1,%2,%3}, {%4,%5,%6,%7}, {%8,%9}, {%0,%1,%2,%3};\n"
        : "+f"(d[0]), "+f"(d[1]), "+f"(d[2]), "+f"(d[3])
        : "r"(a[0]), "r"(a[1]), "r"(a[2]), "r"(a[3]), "r"(b[0]), "r"(b[1]));
}

__device__ __forceinline__ void ldsm_x4(unsigned* r, unsigned addr) {
    asm volatile("ldmatrix.sync.aligned.m8n8.x4.shared.b16 {%0,%1,%2,%3}, [%4];"
                 : "=r"(r[0]), "=r"(r[1]), "=r"(r[2]), "=r"(r[3]) : "r"(addr));
}
__device__ __forceinline__ void ldsm_x2(unsigned* r, unsigned addr) {
    asm volatile("ldmatrix.sync.aligned.m8n8.x2.shared.b16 {%0,%1}, [%2];"
                 : "=r"(r[0]), "=r"(r[1]) : "r"(addr));
}

// ---------------- prep kernels ----------------
__global__ void __launch_bounds__(256) k_prepX(const float* __restrict__ x) {
    int idx = blockIdx.x * 256 + threadIdx.x;     // over T*N*D, x is (N,T,D)
    int k = idx & 1023;
    int r = idx >> 10;                            // n*TT + t
    int t = r & 127;
    int n = r >> 7;
    g_X16[(t * NB + n) * DD + k] = __float2half(x[idx]);
}

__global__ void __launch_bounds__(256) k_prepA(const float* __restrict__ A) {
    int idx = blockIdx.x * 256 + threadIdx.x;
    g_A16[idx] = __float2half(A[idx]);
}

__global__ void k_prepW(const float* __restrict__ Wx, const float* __restrict__ Wh,
                        const float* __restrict__ Wattn) {
    __shared__ float tile[32][33];
    int k0 = blockIdx.x * 32, n0 = blockIdx.y * 32;
    int tx = threadIdx.x, ty = threadIdx.y;       // block (32,8)
    const float* src; int kb;
    if (k0 < 1024)      { src = Wx;    kb = 0; }
    else if (k0 < 2048) { src = Wh;    kb = 1024; }
    else                { src = Wattn; kb = 2048; }
    #pragma unroll
    for (int i = 0; i < 4; ++i) {
        int r = ty + i * 8;
        tile[r][tx] = src[(k0 - kb + r) * N4 + n0 + tx];
    }
    __syncthreads();
    #pragma unroll
    for (int i = 0; i < 4; ++i) {
        int r = ty + i * 8;
        int n = n0 + r, k = k0 + tx;
        float v = tile[tx][r];
        hf hi = __float2half(v);
        hf lo = __float2half(v - __half2float(hi));
        g_Wh16[n * K3 + k] = hi;
        g_Wl16[n * K3 + k] = lo;
    }
}

__global__ void __launch_bounds__(256) k_init(const float* __restrict__ A) {
    int idx = blockIdx.x * 256 + threadIdx.x;     // over NB*HH
    const float* Ap = A + (size_t)idx * LL;
    float s = 0.f;
    #pragma unroll
    for (int l = 0; l < LL; ++l) s += Ap[l];
    s *= (1.f / 49.f);
    g_h[idx] = s;
    g_c[idx] = s;
    g_h16[idx] = __float2half(s);
}

// ---------------- GEMM tile body: 128x128 tile, nchunks k-chunks of 32 ----------------
// kc semantics: [0,1024)=X (prep), [1024,2048)=h16, [2048,3072)=a16; B = W hi(/lo) at kc.
// LO=true: 2-term hi/lo product (prep Z only). LO=false: single-fp16 W (recurrent path).
#define SMS 5120   // 128*40 halfs per stage per matrix
#define NSTAGE 3

template <bool LO>
__device__ __forceinline__ void gemm_load_chunk(int kc, int buf, int bm, int bn, int tid,
                                                hf* sAd, hf* sBh, hf* sBl) {
    const hf* pA; int kA;
    if (kc < 1024)      { pA = g_X16; kA = kc; }
    else if (kc < 2048) { pA = g_h16; kA = kc - 1024; }
    else                { pA = g_a16; kA = kc - 2048; }
    const int NITER = LO ? 6 : 4;     // (A,Bh,Bl) or (A,Bh) x 512 16B-chunks / 256 thr
    #pragma unroll
    for (int j = 0; j < NITER; ++j) {
        int v = tid + 256 * j;
        int mat = v >> 9;             // 0=A 1=Bh (2=Bl when LO)
        int rem = v & 511;
        int row = rem >> 2, cq = rem & 3;
        int soff = buf * SMS + row * 40 + cq * 8;
        if (mat == 0) {
            cp16(sAd + soff, pA + (bm * 128 + row) * 1024 + kA + cq * 8);
        } else {
            size_t gB = (size_t)(bn * 128 + row) * K3 + kc + cq * 8;
            if (mat == 1) cp16(sBh + soff, g_Wh16 + gB);
            else          cp16(sBl + soff, g_Wl16 + gB);
        }
    }
    asm volatile("cp.async.commit_group;\n" ::);
}

template <bool TOZ, bool LO>
__device__ __forceinline__ void gemm_tile(int kc0, int nchunks, int bm, int bn,
                                          hf* P, hf* sm) {
    hf* sAd = sm;
    hf* sBh = sm + NSTAGE * SMS;
    hf* sBl = sm + 2 * NSTAGE * SMS;
    const int tid  = threadIdx.x;
    const int lane = tid & 31, w = tid >> 5;
    const int wm = w & 1, wn = w >> 1;          // 2x4 warp grid, warp tile 64x32
    const int lr = lane >> 2, lc = lane & 3;

    const unsigned bAd = (unsigned)__cvta_generic_to_shared(sAd);
    const unsigned bBh = (unsigned)__cvta_generic_to_shared(sBh);
    const unsigned bBl = (unsigned)__cvta_generic_to_shared(sBl);
    const unsigned aoff = (unsigned)((wm * 64 + (lane & 7) + ((lane >> 3) & 1) * 8) * 80
                                     + ((lane >> 4) & 1) * 16);
    const unsigned boff = (unsigned)((wn * 32 + (lane & 7)) * 80 + ((lane >> 3) & 1) * 16);

    float d[4][4][4];
    #pragma unroll
    for (int a = 0; a < 4; ++a)
        #pragma unroll
        for (int b2 = 0; b2 < 4; ++b2)
            #pragma unroll
            for (int c = 0; c < 4; ++c) d[a][b2][c] = 0.f;

    gemm_load_chunk<LO>(kc0,      0, bm, bn, tid, sAd, sBh, sBl);
    gemm_load_chunk<LO>(kc0 + 32, 1, bm, bn, tid, sAd, sBh, sBl);

    int cb = 0;
    int lb = 2;
    for (int it = 0; it < nchunks; ++it) {
        asm volatile("cp.async.wait_group 1;\n" ::);
        __syncthreads();
        if (it + 2 < nchunks) {
            gemm_load_chunk<LO>(kc0 + (it + 2) * 32, lb, bm, bn, tid, sAd, sBh, sBl);
            if (++lb == NSTAGE) lb = 0;
        }
        const unsigned cbo = (unsigned)(cb * SMS * 2);
        if (++cb == NSTAGE) cb = 0;
        #pragma unroll
        for (int kt = 0; kt < 32; kt += 16) {
            unsigned ad[4][4], bh[4][2], bl[4][2];
            #pragma unroll
            for (int mt = 0; mt < 4; ++mt) {
                unsigned o = cbo + (unsigned)(mt * 1280 + kt * 2) + aoff;
                ldsm_x4(ad[mt], bAd + o);
            }
            #pragma unroll
            for (int nt = 0; nt < 4; ++nt) {
                unsigned o = cbo + (unsigned)(nt * 640 + kt * 2) + boff;
                ldsm_x2(bh[nt], bBh + o);
                if (LO) ldsm_x2(bl[nt], bBl + o);
            }
            #pragma unroll
            for (int mt = 0; mt < 4; ++mt)
                #pragma unroll
                for (int nt = 0; nt < 4; ++nt) {
                    mma16816(d[mt][nt], ad[mt], bh[nt]);
                    if (LO) mma16816(d[mt][nt], ad[mt], bl[nt]);
                }
        }
        __syncthreads();
    }

    if (TOZ) {
        #pragma unroll
        for (int mt = 0; mt < 4; ++mt) {
            size_t r = (size_t)(bm * 128 + wm * 64 + mt * 16 + lr);
            #pragma unroll
            for (int nt = 0; nt < 4; ++nt) {
                int cN = bn * 128 + wn * 32 + nt * 8 + 2 * lc;
                __half2 v0 = __floats2half2_rn(d[mt][nt][0], d[mt][nt][1]);
                __half2 v1 = __floats2half2_rn(d[mt][nt][2], d[mt][nt][3]);
                *(__half2*)&g_Z16[r * N4 + cN]       = v0;
                *(__half2*)&g_Z16[(r + 8) * N4 + cN] = v1;
            }
        }
    } else {
        #pragma unroll
        for (int mt = 0; mt < 4; ++mt) {
            int r = bm * 128 + wm * 64 + mt * 16 + lr;
            #pragma unroll
            for (int nt = 0; nt < 4; ++nt) {
                int cN = bn * 128 + wn * 32 + nt * 8 + 2 * lc;
                __half2 v0 = __floats2half2_rn(d[mt][nt][0], d[mt][nt][1]);
                __half2 v1 = __floats2half2_rn(d[mt][nt][2], d[mt][nt][3]);
                *(__half2*)&P[r * N4 + cN]       = v0;
                *(__half2*)&P[(r + 8) * N4 + cN] = v1;
            }
        }
    }
}

// ---------------- attention body (256 threads) ----------------
#define ATT_CHUNKS ((HH * LL * 2) / 16)   // 6272 16B chunks
__device__ __forceinline__ void att_body(int n, hf* sA16) {
    const int tid = threadIdx.x;
    const int lane = tid & 31, wid = tid >> 5;
    __shared__ float sh[HH];
    __shared__ float sw[64];

    {
        const uint64_t pol = mkpol_evict_last();
        const uint4* Ap = (const uint4*)(g_A16 + (size_t)n * (HH * LL));
        uint4* dst = (uint4*)sA16;
        for (int i = tid; i < ATT_CHUNKS; i += 256)
            cp16_ll(dst + i, Ap + i, pol);
        asm volatile("cp.async.commit_group;\n" ::);
        for (int i = tid; i < HH; i += 256) sh[i] = g_h[n * HH + i];
        asm volatile("cp.async.wait_group 0;\n" ::);
    }
    __syncthreads();

    // pass 1: scores[l] = sum_h A[h][l] * h[h]
    for (int l = wid; l < LL; l += 8) {
        float acc = 0.f;
        #pragma unroll 8
        for (int h = lane; h < HH; h += 32)
            acc += __half2float(sA16[h * LL + l]) * sh[h];
        #pragma unroll
        for (int off = 16; off; off >>= 1)
            acc += __shfl_xor_sync(0xffffffffu, acc, off);
        if (lane == 0) sw[l] = acc * 0.03125f;    // 1/sqrt(H)
    }
    __syncthreads();

    // softmax over 49 scores (warp 0)
    if (wid == 0) {
        float v0 = (lane < LL) ? sw[lane] : -1e30f;
        float v1 = (lane + 32 < LL) ? sw[lane + 32] : -1e30f;
        float m = fmaxf(v0, v1);
        #pragma unroll
        for (int off = 16; off; off >>= 1)
            m = fmaxf(m, __shfl_xor_sync(0xffffffffu, m, off));
        float e0 = (lane < LL) ? __expf(v0 - m) : 0.f;
        float e1 = (lane + 32 < LL) ? __expf(v1 - m) : 0.f;
        float s = e0 + e1;
        #pragma unroll
        for (int off = 16; off; off >>= 1)
            s += __shfl_xor_sync(0xffffffffu, s, off);
        float inv = 1.f / s;
        if (lane < LL) sw[lane] = e0 * inv;
        if (lane + 32 < LL) sw[lane + 32] = e1 * inv;
    }
    __syncthreads();

    // pass 2: attn[h] = sum_l w[l] * A[h][l]
    for (int h = tid; h < HH; h += 256) {
        const hf* row = sA16 + h * LL;
        float acc = 0.f;
        #pragma unroll
        for (int l = 0; l < LL; ++l) acc += sw[l] * __half2float(row[l]);
        g_a16[n * HH + h] = __float2half(acc);
    }
}

// ---------------- fused per-step kernel: h-GEMM (blocks 0..127) + attention (128..383) ----------------
__global__ void __launch_bounds__(256) k_fused() {
    extern __shared__ hf smu[];
    if (blockIdx.x < 128) {
        int bid = blockIdx.x;
        int bm = bid & 1, bn = (bid >> 1) & 31, z = bid >> 6;   // split-K=2 over h slice
        gemm_tile<false, false>(1024 + z * 512, 16, bm, bn, z ? g_P1 : g_P0, smu);
    } else {
        att_body(blockIdx.x - 128, smu);
    }
}

// ---------------- attn-slice GEMM (after k_fused) ----------------
__global__ void __launch_bounds__(256) k_gemm2() {
    extern __shared__ hf smu[];
    int bm = blockIdx.x, bn = blockIdx.y, z = blockIdx.z;
    gemm_tile<false, false>(2048 + z * 512, 16, bm, bn, z ? g_P3 : g_P2, smu);
}

// ---------------- prep GEMM: Z = X @ Wx for all t (keeps 2-term hi/lo precision) ----------------
__global__ void __launch_bounds__(256) k_gemmZ() {
    extern __shared__ hf smu[];
    gemm_tile<true, true>(0, 32, blockIdx.x, blockIdx.y, nullptr, smu);
}

// ---------------- per-step gates + state update + output + h fp16 ----------------
__global__ void __launch_bounds__(256) k_gates(const float* __restrict__ bvec,
                                               float* __restrict__ out, int t) {
    int idx = blockIdx.x * 256 + threadIdx.x;    // over NB*HH
    int n = idx >> 10, j = idx & 1023;
    int base = n * N4 + j;
    const hf* Zt = g_Z16 + (size_t)t * NB * N4;
    float a0 = __half2float(g_P0[base])        + __half2float(g_P1[base])
             + __half2float(g_P2[base])        + __half2float(g_P3[base])
             + __half2float(Zt[base])          + bvec[j];
    float a1 = __half2float(g_P0[base + 1024]) + __half2float(g_P1[base + 1024])
             + __half2float(g_P2[base + 1024]) + __half2float(g_P3[base + 1024])
             + __half2float(Zt[base + 1024])   + bvec[j + 1024];
    float a2 = __half2float(g_P0[base + 2048]) + __half2float(g_P1[base + 2048])
             + __half2float(g_P2[base + 2048]) + __half2float(g_P3[base + 2048])
             + __half2float(Zt[base + 2048])   + bvec[j + 2048];
    float a3 = __half2float(g_P0[base + 3072]) + __half2float(g_P1[base + 3072])
             + __half2float(g_P2[base + 3072]) + __half2float(g_P3[base + 3072])
             + __half2float(Zt[base + 3072])   + bvec[j + 3072];
    float ig = 1.f / (1.f + expf(-a0));
    float fg = 1.f / (1.f + expf(-a1));
    float og = 1.f / (1.f + expf(-a2));
    float gg = tanhf(a3);
    float c = fg * g_c[idx] + ig * gg;
    g_c[idx] = c;
    float hn = og * tanhf(c);
    g_h[idx] = hn;
    out[(n * TT + t) * HH + j] = hn;
    g_h16[idx] = __float2half(hn);
}

// ---------------- launch ----------------
extern "C" void kernel_launch(void* const* d_in, const int* in_sizes, int n_in,
                              void* d_out, int out_size) {
    (void)in_sizes; (void)n_in; (void)out_size;
    const float* x     = (const float*)d_in[0];
    const float* A     = (const float*)d_in[1];
    const float* Wx    = (const float*)d_in[2];
    const float* Wh    = (const float*)d_in[3];
    const float* Wattn = (const float*)d_in[4];
    const float* bvec  = (const float*)d_in[5];
    float* out = (float*)d_out;

    const int gemmSmem = 3 * NSTAGE * SMS * (int)sizeof(hf);   // 92160
    const int attSmem  = HH * LL * (int)sizeof(hf);            // 100352 (>= gemmSmem)
    cudaFuncSetAttribute(k_gemmZ, cudaFuncAttributeMaxDynamicSharedMemorySize, gemmSmem);
    cudaFuncSetAttribute(k_gemm2, cudaFuncAttributeMaxDynamicSharedMemorySize, gemmSmem);
    cudaFuncSetAttribute(k_fused, cudaFuncAttributeMaxDynamicSharedMemorySize, attSmem);

    // prep
    k_prepX<<<(TT * NB * DD) / 256, 256>>>(x);
    k_prepA<<<(NB * HH * LL) / 256, 256>>>(A);
    k_prepW<<<dim3(K3 / 32, N4 / 32), dim3(32, 8)>>>(Wx, Wh, Wattn);
    k_init<<<(NB * HH) / 256, 256>>>(A);

    // one big batched GEMM: Z[t] = x_t @ Wx for ALL t (2-term hi/lo, full precision)
    k_gemmZ<<<dim3(TT * NB / 128, 32), 256, gemmSmem>>>();

    for (int t = 0; t < TT; ++t) {
        k_fused<<<384, 256, attSmem>>>();                       // h-GEMM || attention
        k_gemm2<<<dim3(2, 32, 2), 256, gemmSmem>>>();           // attn-slice GEMM
        k_gates<<<(NB * HH) / 256, 256>>>(bvec, out, t);
    }
}

// round 16
// speedup vs baseline: 2.5884x; 1.1140x over previous
#include <cuda_runtime.h>
#include <cuda_fp16.h>
#include <cstdint>

#define NB 256
#define TT 128
#define DD 1024
#define HH 1024
#define LL 49
#define K3 3072
#define N4 4096

typedef __half hf;

// ---------------- scratch (static device globals; no runtime allocation) ----------------
__device__ __align__(256) hf    g_X16[TT * NB * DD];   // x fp16, [t][n][k]
__device__ __align__(256) hf    g_A16[NB * HH * LL];   // A fp16 (attention only)
__device__ __align__(256) hf    g_W16[N4 * K3];        // W concat transposed [n][k], fp16
__device__ __align__(256) float g_c[NB * HH];
__device__ __align__(256) hf    g_h16[NB * HH];
__device__ __align__(256) hf    g_a16[NB * HH];        // attn fp16
__device__ __align__(256) hf    g_P0[NB * N4];         // h-slice partial z=0 (fp16)
__device__ __align__(256) hf    g_P1[NB * N4];         // h-slice partial z=1
__device__ __align__(256) hf    g_P2[NB * N4];         // attn-slice partial z=0
__device__ __align__(256) hf    g_P3[NB * N4];         // attn-slice partial z=1
__device__ __align__(256) hf    g_Z16[(size_t)TT * NB * N4];  // x@Wx for all t, fp16

__device__ __forceinline__ void cp16(const void* smem_dst, const void* gsrc) {
    unsigned s = (unsigned)__cvta_generic_to_shared((void*)smem_dst);
    asm volatile("cp.async.cg.shared.global [%0], [%1], 16;\n" :: "r"(s), "l"(gsrc));
}
__device__ __forceinline__ void cp16_ll(const void* smem_dst, const void* gsrc, uint64_t pol) {
    unsigned s = (unsigned)__cvta_generic_to_shared((void*)smem_dst);
    asm volatile("cp.async.cg.shared.global.L2::cache_hint [%0], [%1], 16, %2;\n"
                 :: "r"(s), "l"(gsrc), "l"(pol));
}
__device__ __forceinline__ uint64_t mkpol_evict_last() {
    uint64_t pol;
    asm("createpolicy.fractional.L2::evict_last.b64 %0, 1.0;" : "=l"(pol));
    return pol;
}

__device__ __forceinline__ void mma16816(float* d, const unsigned* a, const unsigned* b) {
    asm volatile(
        "mma.sync.aligned.m16n8k16.row.col.f32.f16.f16.f32 "
        "{%0,%1,%2,%3}, {%4,%5,%6,%7}, {%8,%9}, {%0,%1,%2,%3};\n"
        : "+f"(d[0]), "+f"(d[1]), "+f"(d[2]), "+f"(d[3])
        : "r"(a[0]), "r"(a[1]), "r"(a[2]), "r"(a[3]), "r"(b[0]), "r"(b[1]));
}

__device__ __forceinline__ void ldsm_x4(unsigned* r, unsigned addr) {
    asm volatile("ldmatrix.sync.aligned.m8n8.x4.shared.b16 {%0,%1,%2,%3}, [%4];"
                 : "=r"(r[0]), "=r"(r[1]), "=r"(r[2]), "=r"(r[3]) : "r"(addr));
}
__device__ __forceinline__ void ldsm_x2(unsigned* r, unsigned addr) {
    asm volatile("ldmatrix.sync.aligned.m8n8.x2.shared.b16 {%0,%1}, [%2];"
                 : "=r"(r[0]), "=r"(r[1]) : "r"(addr));
}

// ---------------- prep kernels ----------------
__global__ void __launch_bounds__(256) k_prepX(const float* __restrict__ x) {
    int idx = blockIdx.x * 256 + threadIdx.x;     // over T*N*D, x is (N,T,D)
    int k = idx & 1023;
    int r = idx >> 10;                            // n*TT + t
    int t = r & 127;
    int n = r >> 7;
    g_X16[(t * NB + n) * DD + k] = __float2half(x[idx]);
}

__global__ void __launch_bounds__(256) k_prepA(const float* __restrict__ A) {
    int idx = blockIdx.x * 256 + threadIdx.x;
    g_A16[idx] = __float2half(A[idx]);
}

__global__ void k_prepW(const float* __restrict__ Wx, const float* __restrict__ Wh,
                        const float* __restrict__ Wattn) {
    __shared__ float tile[32][33];
    int k0 = blockIdx.x * 32, n0 = blockIdx.y * 32;
    int tx = threadIdx.x, ty = threadIdx.y;       // block (32,8)
    const float* src; int kb;
    if (k0 < 1024)      { src = Wx;    kb = 0; }
    else if (k0 < 2048) { src = Wh;    kb = 1024; }
    else                { src = Wattn; kb = 2048; }
    #pragma unroll
    for (int i = 0; i < 4; ++i) {
        int r = ty + i * 8;
        tile[r][tx] = src[(k0 - kb + r) * N4 + n0 + tx];
    }
    __syncthreads();
    #pragma unroll
    for (int i = 0; i < 4; ++i) {
        int r = ty + i * 8;
        int n = n0 + r, k = k0 + tx;
        g_W16[n * K3 + k] = __float2half(tile[tx][r]);
    }
}

__global__ void __launch_bounds__(256) k_init(const float* __restrict__ A) {
    int idx = blockIdx.x * 256 + threadIdx.x;     // over NB*HH
    const float* Ap = A + (size_t)idx * LL;
    float s = 0.f;
    #pragma unroll
    for (int l = 0; l < LL; ++l) s += Ap[l];
    s *= (1.f / 49.f);
    g_c[idx] = s;
    g_h16[idx] = __float2half(s);
}

// ---------------- GEMM tile body: 128x128 tile, nchunks k-chunks of 32 ----------------
// kc semantics: [0,1024)=X (prep), [1024,2048)=h16, [2048,3072)=a16; B = g_W16 at kc.
#define SMS 5120   // 128*40 halfs per stage per matrix
#define NSTAGE 3

__device__ __forceinline__ void gemm_load_chunk(int kc, int buf, int bm, int bn, int tid,
                                                hf* sAd, hf* sBh) {
    const hf* pA; int kA;
    if (kc < 1024)      { pA = g_X16; kA = kc; }
    else if (kc < 2048) { pA = g_h16; kA = kc - 1024; }
    else                { pA = g_a16; kA = kc - 2048; }
    #pragma unroll
    for (int j = 0; j < 4; ++j) {
        int v = tid + 256 * j;        // 0..1023
        int mat = v >> 9;             // 0=A 1=B
        int rem = v & 511;
        int row = rem >> 2, cq = rem & 3;
        int soff = buf * SMS + row * 40 + cq * 8;
        if (mat == 0) {
            cp16(sAd + soff, pA + (bm * 128 + row) * 1024 + kA + cq * 8);
        } else {
            cp16(sBh + soff, g_W16 + (size_t)(bn * 128 + row) * K3 + kc + cq * 8);
        }
    }
    asm volatile("cp.async.commit_group;\n" ::);
}

template <bool TOZ>
__device__ __forceinline__ void gemm_tile(int kc0, int nchunks, int bm, int bn,
                                          hf* P, hf* sm) {
    hf* sAd = sm;
    hf* sBh = sm + NSTAGE * SMS;
    const int tid  = threadIdx.x;
    const int lane = tid & 31, w = tid >> 5;
    const int wm = w & 1, wn = w >> 1;          // 2x4 warp grid, warp tile 64x32
    const int lr = lane >> 2, lc = lane & 3;

    const unsigned bAd = (unsigned)__cvta_generic_to_shared(sAd);
    const unsigned bBh = (unsigned)__cvta_generic_to_shared(sBh);
    const unsigned aoff = (unsigned)((wm * 64 + (lane & 7) + ((lane >> 3) & 1) * 8) * 80
                                     + ((lane >> 4) & 1) * 16);
    const unsigned boff = (unsigned)((wn * 32 + (lane & 7)) * 80 + ((lane >> 3) & 1) * 16);

    float d[4][4][4];
    #pragma unroll
    for (int a = 0; a < 4; ++a)
        #pragma unroll
        for (int b2 = 0; b2 < 4; ++b2)
            #pragma unroll
            for (int c = 0; c < 4; ++c) d[a][b2][c] = 0.f;

    gemm_load_chunk(kc0,      0, bm, bn, tid, sAd, sBh);
    gemm_load_chunk(kc0 + 32, 1, bm, bn, tid, sAd, sBh);

    int cb = 0;
    int lb = 2;
    for (int it = 0; it < nchunks; ++it) {
        asm volatile("cp.async.wait_group 1;\n" ::);
        __syncthreads();
        if (it + 2 < nchunks) {
            gemm_load_chunk(kc0 + (it + 2) * 32, lb, bm, bn, tid, sAd, sBh);
            if (++lb == NSTAGE) lb = 0;
        }
        const unsigned cbo = (unsigned)(cb * SMS * 2);
        if (++cb == NSTAGE) cb = 0;
        #pragma unroll
        for (int kt = 0; kt < 32; kt += 16) {
            unsigned ad[4][4], bh[4][2];
            #pragma unroll
            for (int mt = 0; mt < 4; ++mt) {
                unsigned o = cbo + (unsigned)(mt * 1280 + kt * 2) + aoff;
                ldsm_x4(ad[mt], bAd + o);
            }
            #pragma unroll
            for (int nt = 0; nt < 4; ++nt) {
                unsigned o = cbo + (unsigned)(nt * 640 + kt * 2) + boff;
                ldsm_x2(bh[nt], bBh + o);
            }
            #pragma unroll
            for (int mt = 0; mt < 4; ++mt)
                #pragma unroll
                for (int nt = 0; nt < 4; ++nt)
                    mma16816(d[mt][nt], ad[mt], bh[nt]);
        }
        __syncthreads();
    }

    if (TOZ) {
        #pragma unroll
        for (int mt = 0; mt < 4; ++mt) {
            size_t r = (size_t)(bm * 128 + wm * 64 + mt * 16 + lr);
            #pragma unroll
            for (int nt = 0; nt < 4; ++nt) {
                int cN = bn * 128 + wn * 32 + nt * 8 + 2 * lc;
                __half2 v0 = __floats2half2_rn(d[mt][nt][0], d[mt][nt][1]);
                __half2 v1 = __floats2half2_rn(d[mt][nt][2], d[mt][nt][3]);
                *(__half2*)&g_Z16[r * N4 + cN]       = v0;
                *(__half2*)&g_Z16[(r + 8) * N4 + cN] = v1;
            }
        }
    } else {
        #pragma unroll
        for (int mt = 0; mt < 4; ++mt) {
            int r = bm * 128 + wm * 64 + mt * 16 + lr;
            #pragma unroll
            for (int nt = 0; nt < 4; ++nt) {
                int cN = bn * 128 + wn * 32 + nt * 8 + 2 * lc;
                __half2 v0 = __floats2half2_rn(d[mt][nt][0], d[mt][nt][1]);
                __half2 v1 = __floats2half2_rn(d[mt][nt][2], d[mt][nt][3]);
                *(__half2*)&P[r * N4 + cN]       = v0;
                *(__half2*)&P[(r + 8) * N4 + cN] = v1;
            }
        }
    }
}

// ---------------- attention body (256 threads) ----------------
#define ATT_CHUNKS ((HH * LL * 2) / 16)   // 6272 16B chunks
__device__ __forceinline__ void att_body(int n, hf* sA16) {
    const int tid = threadIdx.x;
    const int lane = tid & 31, wid = tid >> 5;
    __shared__ float sh[HH];
    __shared__ float sw[64];

    {
        const uint64_t pol = mkpol_evict_last();
        const uint4* Ap = (const uint4*)(g_A16 + (size_t)n * (HH * LL));
        uint4* dst = (uint4*)sA16;
        for (int i = tid; i < ATT_CHUNKS; i += 256)
            cp16_ll(dst + i, Ap + i, pol);
        asm volatile("cp.async.commit_group;\n" ::);
        for (int i = tid; i < HH; i += 256) sh[i] = __half2float(g_h16[n * HH + i]);
        asm volatile("cp.async.wait_group 0;\n" ::);
    }
    __syncthreads();

    // pass 1: scores[l] = sum_h A[h][l] * h[h]
    for (int l = wid; l < LL; l += 8) {
        float acc = 0.f;
        #pragma unroll 8
        for (int h = lane; h < HH; h += 32)
            acc += __half2float(sA16[h * LL + l]) * sh[h];
        #pragma unroll
        for (int off = 16; off; off >>= 1)
            acc += __shfl_xor_sync(0xffffffffu, acc, off);
        if (lane == 0) sw[l] = acc * 0.03125f;    // 1/sqrt(H)
    }
    __syncthreads();

    // softmax over 49 scores (warp 0)
    if (wid == 0) {
        float v0 = (lane < LL) ? sw[lane] : -1e30f;
        float v1 = (lane + 32 < LL) ? sw[lane + 32] : -1e30f;
        float m = fmaxf(v0, v1);
        #pragma unroll
        for (int off = 16; off; off >>= 1)
            m = fmaxf(m, __shfl_xor_sync(0xffffffffu, m, off));
        float e0 = (lane < LL) ? __expf(v0 - m) : 0.f;
        float e1 = (lane + 32 < LL) ? __expf(v1 - m) : 0.f;
        float s = e0 + e1;
        #pragma unroll
        for (int off = 16; off; off >>= 1)
            s += __shfl_xor_sync(0xffffffffu, s, off);
        float inv = 1.f / s;
        if (lane < LL) sw[lane] = e0 * inv;
        if (lane + 32 < LL) sw[lane + 32] = e1 * inv;
    }
    __syncthreads();

    // pass 2: attn[h] = sum_l w[l] * A[h][l]
    for (int h = tid; h < HH; h += 256) {
        const hf* row = sA16 + h * LL;
        float acc = 0.f;
        #pragma unroll
        for (int l = 0; l < LL; ++l) acc += sw[l] * __half2float(row[l]);
        g_a16[n * HH + h] = __float2half(acc);
    }
}

// ---------------- fused per-step kernel: h-GEMM (blocks 0..127) + attention (128..383) ----------------
__global__ void __launch_bounds__(256) k_fused() {
    extern __shared__ hf smu[];
    if (blockIdx.x < 128) {
        int bid = blockIdx.x;
        int bm = bid & 1, bn = (bid >> 1) & 31, z = bid >> 6;   // split-K=2 over h slice
        gemm_tile<false>(1024 + z * 512, 16, bm, bn, z ? g_P1 : g_P0, smu);
    } else {
        att_body(blockIdx.x - 128, smu);
    }
}

// ---------------- attn-slice GEMM (after k_fused) ----------------
__global__ void __launch_bounds__(256) k_gemm2() {
    extern __shared__ hf smu[];
    int bm = blockIdx.x, bn = blockIdx.y, z = blockIdx.z;
    gemm_tile<false>(2048 + z * 512, 16, bm, bn, z ? g_P3 : g_P2, smu);
}

// ---------------- prep GEMM: Z = X @ Wx for all t ----------------
__global__ void __launch_bounds__(256) k_gemmZ() {
    extern __shared__ hf smu[];
    gemm_tile<true>(0, 32, blockIdx.x, blockIdx.y, nullptr, smu);
}

// ---------------- per-step gates + state update + output + h fp16 ----------------
__global__ void __launch_bounds__(256) k_gates(const float* __restrict__ bvec,
                                               float* __restrict__ out, int t) {
    int idx = blockIdx.x * 256 + threadIdx.x;    // over NB*HH
    int n = idx >> 10, j = idx & 1023;
    int base = n * N4 + j;
    const hf* Zt = g_Z16 + (size_t)t * NB * N4;
    float a0 = __half2float(g_P0[base])        + __half2float(g_P1[base])
             + __half2float(g_P2[base])        + __half2float(g_P3[base])
             + __half2float(Zt[base])          + bvec[j];
    float a1 = __half2float(g_P0[base + 1024]) + __half2float(g_P1[base + 1024])
             + __half2float(g_P2[base + 1024]) + __half2float(g_P3[base + 1024])
             + __half2float(Zt[base + 1024])   + bvec[j + 1024];
    float a2 = __half2float(g_P0[base + 2048]) + __half2float(g_P1[base + 2048])
             + __half2float(g_P2[base + 2048]) + __half2float(g_P3[base + 2048])
             + __half2float(Zt[base + 2048])   + bvec[j + 2048];
    float a3 = __half2float(g_P0[base + 3072]) + __half2float(g_P1[base + 3072])
             + __half2float(g_P2[base + 3072]) + __half2float(g_P3[base + 3072])
             + __half2float(Zt[base + 3072])   + bvec[j + 3072];
    float ig = 1.f / (1.f + expf(-a0));
    float fg = 1.f / (1.f + expf(-a1));
    float og = 1.f / (1.f + expf(-a2));
    float gg = tanhf(a3);
    float c = fg * g_c[idx] + ig * gg;
    g_c[idx] = c;
    float hn = og * tanhf(c);
    out[(n * TT + t) * HH + j] = hn;
    g_h16[idx] = __float2half(hn);
}

// ---------------- launch ----------------
extern "C" void kernel_launch(void* const* d_in, const int* in_sizes, int n_in,
                              void* d_out, int out_size) {
    (void)in_sizes; (void)n_in; (void)out_size;
    const float* x     = (const float*)d_in[0];
    const float* A     = (const float*)d_in[1];
    const float* Wx    = (const float*)d_in[2];
    const float* Wh    = (const float*)d_in[3];
    const float* Wattn = (const float*)d_in[4];
    const float* bvec  = (const float*)d_in[5];
    float* out = (float*)d_out;

    const int gemmSmem = 2 * NSTAGE * SMS * (int)sizeof(hf);   // 61440
    const int attSmem  = HH * LL * (int)sizeof(hf);            // 100352 (>= gemmSmem)
    cudaFuncSetAttribute(k_gemmZ, cudaFuncAttributeMaxDynamicSharedMemorySize, gemmSmem);
    cudaFuncSetAttribute(k_gemm2, cudaFuncAttributeMaxDynamicSharedMemorySize, gemmSmem);
    cudaFuncSetAttribute(k_fused, cudaFuncAttributeMaxDynamicSharedMemorySize, attSmem);

    // prep
    k_prepX<<<(TT * NB * DD) / 256, 256>>>(x);
    k_prepA<<<(NB * HH * LL) / 256, 256>>>(A);
    k_prepW<<<dim3(K3 / 32, N4 / 32), dim3(32, 8)>>>(Wx, Wh, Wattn);
    k_init<<<(NB * HH) / 256, 256>>>(A);

    // one big batched GEMM: Z[t] = x_t @ Wx for ALL t
    k_gemmZ<<<dim3(TT * NB / 128, 32), 256, gemmSmem>>>();

    for (int t = 0; t < TT; ++t) {
        k_fused<<<384, 256, attSmem>>>();                       // h-GEMM || attention
        k_gemm2<<<dim3(2, 32, 2), 256, gemmSmem>>>();           // attn-slice GEMM
        k_gates<<<(NB * HH) / 256, 256>>>(bvec, out, t);
    }
}